// round 11
// baseline (speedup 1.0000x reference)
#include <cuda_runtime.h>
#include <math.h>

#define Bb   2
#define Tt   512
#define Hh   16
#define BHT  16384
#define MSZ  (1024*1024)

// ---------------- scratch ----------------------------------------------------
__device__ float g_q [BHT*64];
__device__ float g_k [BHT*64];
__device__ float g_v [BHT*64];
__device__ float g_km[BHT*32];
__device__ float g_k2[BHT];
__device__ float g_U [BHT*128];
__device__ float g_m [BHT*32];
__device__ float g_c [BHT];
__device__ float g_pacc[2][BHT*64];
__device__ float g_psum[2][BHT];
__device__ float g_ao[Bb*Tt*1024];
// bf16 split-packed operands: uint2 = (ah_pair, al_pair) per 2 k-elements
__device__ uint2 g_xs[MSZ/2];        // A  [1024 rows][512 kp]
__device__ uint2 g_ws[4*(MSZ/2)];    // W  [512 kp][1024 n] x4

// ---------------- bf16 split helpers -------------------------------------------
__device__ __forceinline__ uint2 sbf(float a, float b) {
    unsigned ph;
    asm("cvt.rn.bf16x2.f32 %0,%1,%2;" : "=r"(ph) : "f"(b), "f"(a));
    float ra = a - __uint_as_float(ph << 16);
    float rb = b - __uint_as_float(ph & 0xffff0000u);
    unsigned pl;
    asm("cvt.rn.bf16x2.f32 %0,%1,%2;" : "=r"(pl) : "f"(rb), "f"(ra));
    return make_uint2(ph, pl);
}

// ---------------- tf32 helpers (attention only) --------------------------------
__device__ __forceinline__ unsigned tf32of(float x) {
    unsigned r; asm("cvt.rna.tf32.f32 %0,%1;" : "=r"(r) : "f"(x)); return r;
}
__device__ __forceinline__ uint2 spl(float x) {
    unsigned h = tf32of(x);
    unsigned l = tf32of(x - __uint_as_float(h));
    return make_uint2(h, l);
}
__device__ __forceinline__ void mma8(float* c,
    unsigned a0, unsigned a1, unsigned a2, unsigned a3,
    unsigned b0, unsigned b1)
{
    asm volatile(
        "mma.sync.aligned.m16n8k8.row.col.f32.tf32.tf32.f32 "
        "{%0,%1,%2,%3},{%4,%5,%6,%7},{%8,%9},{%0,%1,%2,%3};"
        : "+f"(c[0]), "+f"(c[1]), "+f"(c[2]), "+f"(c[3])
        : "r"(a0), "r"(a1), "r"(a2), "r"(a3), "r"(b0), "r"(b1));
}
__device__ __forceinline__ void mma16(float* c,
    unsigned a0, unsigned a1, unsigned a2, unsigned a3,
    unsigned b0, unsigned b1)
{
    asm volatile(
        "mma.sync.aligned.m16n8k16.row.col.f32.bf16.bf16.f32 "
        "{%0,%1,%2,%3},{%4,%5,%6,%7},{%8,%9},{%0,%1,%2,%3};"
        : "+f"(c[0]), "+f"(c[1]), "+f"(c[2]), "+f"(c[3])
        : "r"(a0), "r"(a1), "r"(a2), "r"(a3), "r"(b0), "r"(b1));
}

// ---------------- split kernels -------------------------------------------------
__global__ void splitA(const float* __restrict__ src, uint2* __restrict__ dst)
{
    int idx = blockIdx.x * 256 + threadIdx.x;
    float4 v0 = *(const float4*)&src[idx * 8];
    float4 v1 = *(const float4*)&src[idx * 8 + 4];
    dst[idx * 4 + 0] = sbf(v0.x, v0.y);
    dst[idx * 4 + 1] = sbf(v0.z, v0.w);
    dst[idx * 4 + 2] = sbf(v1.x, v1.y);
    dst[idx * 4 + 3] = sbf(v1.z, v1.w);
}

// fused: all 4 weights in one launch (blockIdx.x >> 9 selects matrix)
__global__ void splitW4(const float* __restrict__ W0, const float* __restrict__ W1,
                        const float* __restrict__ W2, const float* __restrict__ W3)
{
    int m = blockIdx.x >> 9;
    const float* W = (m == 0) ? W0 : (m == 1) ? W1 : (m == 2) ? W2 : W3;
    uint2* dst = g_ws + m * (MSZ / 2);
    int idx = (blockIdx.x & 511) * 256 + threadIdx.x;
    int kp = idx >> 8;
    int n4 = (idx & 255) * 4;
    float4 r0 = *(const float4*)&W[(2 * kp) * 1024 + n4];
    float4 r1 = *(const float4*)&W[(2 * kp + 1) * 1024 + n4];
    dst[kp * 1024 + n4 + 0] = sbf(r0.x, r1.x);
    dst[kp * 1024 + n4 + 1] = sbf(r0.y, r1.y);
    dst[kp * 1024 + n4 + 2] = sbf(r0.z, r1.z);
    dst[kp * 1024 + n4 + 3] = sbf(r0.w, r1.w);
}

// ---------------- GEMM (3x bf16, 128x128 tile) ---------------------------------
// mode 0: A = g_xs (x), W = g_ws + z*(MSZ/2), head-split store (2 heads/block)
// mode 1: A = g_xs (ao re-split), W = g_ws + 3*(MSZ/2), plain store to Cout
#define SA_STR 18
#define SB_STR 132
#define GEMM_SMEM ((128*SA_STR + 16*SB_STR) * 8)

__global__ void __launch_bounds__(256) gemm_tc(float* __restrict__ Cout, int mode)
{
    extern __shared__ uint2 sm2[];
    uint2* sA = sm2;                     // [128][SA_STR]
    uint2* sB = sm2 + 128 * SA_STR;      // [16][SB_STR]

    int z = blockIdx.z;
    const uint4* Wm = (const uint4*)(g_ws + (mode == 0 ? z : 3) * (MSZ/2));
    const uint4* Am = (const uint4*)g_xs;

    int tid  = threadIdx.x;
    int lane = tid & 31;
    int wid  = tid >> 5;
    int wm   = wid & 3;                  // 4 warps over M
    int wn   = wid >> 2;                 // 2 warps over N (64 cols each)
    int g    = lane >> 2;
    int tg   = lane & 3;
    int row0 = blockIdx.y * 128;
    int col0 = blockIdx.x * 128;

    // A tile: 128 rows x 8 uint4 (16 kp) -> 4 uint4 per thread
    int aRow[4], aK4[4], sAi[4];
    #pragma unroll
    for (int e = 0; e < 4; e++) {
        int idx = tid + e * 256;
        aRow[e] = idx >> 3; aK4[e] = idx & 7;
        sAi[e]  = aRow[e] * SA_STR + aK4[e] * 2;
    }
    // B tile: 16 kp x 64 uint4 (128 cols) -> 4 consecutive uint4 per thread
    int bKp = tid >> 4, bC4 = tid & 15;
    int sBi = bKp * SB_STR + bC4 * 8;                  // uint2 index
    int bGi = bKp * 512 + col0 / 2 + bC4 * 4;          // uint4 global index

    float acc[2][8][4];
    #pragma unroll
    for (int mt = 0; mt < 2; mt++)
        #pragma unroll
        for (int nt = 0; nt < 8; nt++)
            #pragma unroll
            for (int e = 0; e < 4; e++) acc[mt][nt][e] = 0.f;

    uint4 av[4], bv[4];
    #pragma unroll
    for (int e = 0; e < 4; e++)
        av[e] = Am[(row0 + aRow[e]) * 256 + aK4[e]];
    #pragma unroll
    for (int e = 0; e < 4; e++)
        bv[e] = Wm[bGi + e];

    for (int t = 0; t < 32; t++) {
        __syncthreads();
        #pragma unroll
        for (int e = 0; e < 4; e++)
            *(uint4*)&sA[sAi[e]] = av[e];
        #pragma unroll
        for (int e = 0; e < 4; e++)
            *(uint4*)&sB[sBi + e * 2] = bv[e];
        __syncthreads();

        if (t < 31) {
            #pragma unroll
            for (int e = 0; e < 4; e++)
                av[e] = Am[(row0 + aRow[e]) * 256 + (t + 1) * 8 + aK4[e]];
            #pragma unroll
            for (int e = 0; e < 4; e++)
                bv[e] = Wm[(t + 1) * 16 * 512 + bGi + e];
        }

        #pragma unroll
        for (int ks = 0; ks < 2; ks++) {
            uint2 Afr[2][4];
            #pragma unroll
            for (int mt = 0; mt < 2; mt++) {
                int rb = (wm * 32 + mt * 16 + g) * SA_STR + ks * 8 + tg;
                Afr[mt][0] = sA[rb];
                Afr[mt][2] = sA[rb + 4];
                Afr[mt][1] = sA[rb + 8 * SA_STR];
                Afr[mt][3] = sA[rb + 8 * SA_STR + 4];
            }
            #pragma unroll
            for (int nt = 0; nt < 8; nt++) {
                int cb = (ks * 8 + tg) * SB_STR + wn * 64 + nt * 8 + g;
                uint2 B0 = sB[cb];
                uint2 B1 = sB[cb + 4 * SB_STR];
                #pragma unroll
                for (int mt = 0; mt < 2; mt++) {
                    float* c = acc[mt][nt];
                    mma16(c, Afr[mt][0].x, Afr[mt][1].x, Afr[mt][2].x, Afr[mt][3].x,
                          B0.x, B1.x);                               // hi*hi
                    mma16(c, Afr[mt][0].x, Afr[mt][1].x, Afr[mt][2].x, Afr[mt][3].x,
                          B0.y, B1.y);                               // hi*lo
                    mma16(c, Afr[mt][0].y, Afr[mt][1].y, Afr[mt][2].y, Afr[mt][3].y,
                          B0.x, B1.x);                               // lo*hi
                }
            }
        }
    }

    if (mode == 1) {
        #pragma unroll
        for (int mt = 0; mt < 2; mt++) {
            int row = row0 + wm * 32 + mt * 16 + g;
            #pragma unroll
            for (int nt = 0; nt < 8; nt++) {
                int col = col0 + wn * 64 + nt * 8 + 2 * tg;
                *(float2*)&Cout[row * 1024 + col] =
                    make_float2(acc[mt][nt][0], acc[mt][nt][1]);
                *(float2*)&Cout[(row + 8) * 1024 + col] =
                    make_float2(acc[mt][nt][2], acc[mt][nt][3]);
            }
        }
    } else {
        float* dst = (z == 0) ? g_q : (z == 1) ? g_k : g_v;
        #pragma unroll
        for (int mt = 0; mt < 2; mt++) {
            int row = row0 + wm * 32 + mt * 16 + g;
            int b0r = row >> 9, t0r = row & 511;
            int b1r = (row + 8) >> 9, t1r = (row + 8) & 511;
            #pragma unroll
            for (int nt = 0; nt < 8; nt++) {
                int col = wn * 64 + nt * 8 + 2 * tg;   // 0..127 within block
                int h = blockIdx.x * 2 + (col >> 6);
                int dh = col & 63;
                *(float2*)&dst[(((b0r << 4) + h) * 512 + t0r) * 64 + dh] =
                    make_float2(acc[mt][nt][0], acc[mt][nt][1]);
                *(float2*)&dst[(((b1r << 4) + h) * 512 + t1r) * 64 + dh] =
                    make_float2(acc[mt][nt][2], acc[mt][nt][3]);
            }
        }
    }
}

// ---------------- RoPE (in place on g_q, g_k) -------------------------------
__global__ void rope_kernel()
{
    int idx = blockIdx.x * blockDim.x + threadIdx.x;
    if (idx >= BHT * 32) return;
    int tok = idx >> 5;
    int j   = idx & 31;
    int t   = tok & 511;
    float inv = expf(-((float)(2 * j) / 64.0f) * 9.210340371976184f);
    float fr  = (float)t * inv;
    float s, c;
    sincosf(fr, &s, &c);

    float* q = g_q + tok * 64;
    float x1 = q[j], x2 = q[j + 32];
    q[j]      = x1 * c - x2 * s;
    q[j + 32] = x1 * s + x2 * c;

    float* k = g_k + tok * 64;
    x1 = k[j]; x2 = k[j + 32];
    k[j]      = x1 * c - x2 * s;
    k[j + 32] = x1 * s + x2 * c;
}

// ---------------- metric (R4): km, k2, U, m = qm+w, c = q2+|Uq|^2 ------------
__global__ void __launch_bounds__(256) metric_kernel(
    const float* __restrict__ Wqm, const float* __restrict__ Wkm,
    const float* __restrict__ Wmetric)
{
    __shared__ float sWqm[64 * 32];
    __shared__ float sWkm[64 * 32];
    __shared__ float sWm [32 * 128];
    int tid = threadIdx.x;
    for (int i = tid; i < 64 * 32; i += 256) { sWqm[i] = Wqm[i]; sWkm[i] = Wkm[i]; }
    for (int i = tid; i < 32 * 128; i += 256) { sWm[i] = Wmetric[i]; }
    __syncthreads();

    const unsigned FULL = 0xffffffffu;
    int w = tid >> 5, lane = tid & 31;
    int tok = blockIdx.x * 8 + w;

    const float* q = g_q + tok * 64;
    const float* k = g_k + tok * 64;
    float a0 = q[lane], a1 = q[lane + 32];
    float b0 = k[lane], b1 = k[lane + 32];

    float accq = 0.f, acck = 0.f;
    #pragma unroll
    for (int d = 0; d < 32; d++) {
        float qd = __shfl_sync(FULL, a0, d);
        float kd = __shfl_sync(FULL, b0, d);
        accq += qd * sWqm[d * 32 + lane];
        acck += kd * sWkm[d * 32 + lane];
    }
    #pragma unroll
    for (int d = 0; d < 32; d++) {
        float qd = __shfl_sync(FULL, a1, d);
        float kd = __shfl_sync(FULL, b1, d);
        accq += qd * sWqm[(d + 32) * 32 + lane];
        acck += kd * sWkm[(d + 32) * 32 + lane];
    }
    float qmv = 1.f / (1.f + expf(-accq));
    float kmv = 1.f / (1.f + expf(-acck));
    g_km[tok * 32 + lane] = kmv;

    float q2 = qmv * qmv, k2 = kmv * kmv;
    #pragma unroll
    for (int o = 16; o > 0; o >>= 1) {
        q2 += __shfl_xor_sync(FULL, q2, o);
        k2 += __shfl_xor_sync(FULL, k2, o);
    }
    if (lane == 0) g_k2[tok] = k2;

    float u0 = 0.f, u1 = 0.f, u2 = 0.f, u3 = 0.f;
    #pragma unroll
    for (int d = 0; d < 32; d++) {
        float qd = __shfl_sync(FULL, qmv, d);
        float4 wv = *(const float4*)&sWm[d * 128 + lane * 4];
        u0 += qd * wv.x; u1 += qd * wv.y; u2 += qd * wv.z; u3 += qd * wv.w;
    }
    *(float4*)&g_U[tok * 128 + lane * 4] = make_float4(u0, u1, u2, u3);

    float p0 = u0 * qmv, p1 = u1 * qmv, p2 = u2 * qmv, p3 = u3 * qmv;
    #pragma unroll
    for (int o = 16; o > 0; o >>= 1) {
        p0 += __shfl_xor_sync(FULL, p0, o);
        p1 += __shfl_xor_sync(FULL, p1, o);
        p2 += __shfl_xor_sync(FULL, p2, o);
        p3 += __shfl_xor_sync(FULL, p3, o);
    }
    float wd = p0 * u0 + p1 * u1 + p2 * u2 + p3 * u3;
    g_m[tok * 32 + lane] = qmv + wd;
    if (lane == 0)
        g_c[tok] = q2 + p0 * p0 + p1 * p1 + p2 * p2 + p3 * p3;
}

// ---------------- attention via MMA (R7, frozen) -------------------------------
#define KM_STR 66
#define V_STR  66
#define P_STR  66
#define ATTN_SMEM ((32*KM_STR + 64*V_STR + 128*P_STR) * 8 + 64 * 4)

__global__ void __launch_bounds__(256) attn_mma(const float* __restrict__ temp_ptr)
{
    extern __shared__ uint2 smem[];
    uint2* sKm = smem;
    uint2* sV  = sKm + 32 * KM_STR;
    uint2* sP  = sV + 64 * V_STR;
    float* sK2 = (float*)(sP + 128 * P_STR);

    int qt = 3 - (int)(blockIdx.x >> 1);
    int jc = blockIdx.x & 1;
    int bh = blockIdx.y;
    int tok0 = bh * 512 + qt * 128;

    int tid  = threadIdx.x;
    int lane = tid & 31;
    int wid  = tid >> 5;
    int g    = lane >> 2;
    int tg   = lane & 3;
    int r0w  = wid * 16;

    float invT = 1.0f / fmaxf(temp_ptr[0], 0.5f);

    int rA = tok0 + r0w + g;
    int rB = rA + 8;
    int iRelA = qt * 128 + r0w + g;
    int iRelB = iRelA + 8;

    uint2 mm[4][4];
    unsigned uf[4][4][4];
    #pragma unroll
    for (int kk = 0; kk < 4; kk++) {
        int d0 = kk * 8 + tg;
        mm[kk][0] = spl(g_m[rA * 32 + d0]);
        mm[kk][1] = spl(g_m[rB * 32 + d0]);
        mm[kk][2] = spl(g_m[rA * 32 + d0 + 4]);
        mm[kk][3] = spl(g_m[rB * 32 + d0 + 4]);
        float4 uA0 = *(const float4*)&g_U[rA * 128 + d0 * 4];
        float4 uB0 = *(const float4*)&g_U[rB * 128 + d0 * 4];
        float4 uA4 = *(const float4*)&g_U[rA * 128 + (d0 + 4) * 4];
        float4 uB4 = *(const float4*)&g_U[rB * 128 + (d0 + 4) * 4];
        #pragma unroll
        for (int r = 0; r < 4; r++) {
            uf[r][kk][0] = tf32of(((const float*)&uA0)[r]);
            uf[r][kk][1] = tf32of(((const float*)&uB0)[r]);
            uf[r][kk][2] = tf32of(((const float*)&uA4)[r]);
            uf[r][kk][3] = tf32of(((const float*)&uB4)[r]);
        }
    }
    float ci0 = g_c[rA], ci1 = g_c[rB];

    float cpv[8][4];
    #pragma unroll
    for (int nt = 0; nt < 8; nt++)
        #pragma unroll
        for (int e = 0; e < 4; e++) cpv[nt][e] = 0.f;
    float runs0 = 0.f, runs1 = 0.f;

    int sj   = tid >> 2;
    int sgrp = tid & 3;

    for (int jt = jc; jt <= 2 * qt + 1; jt += 2) {
        int j0 = jt * 64;
        int tokJ = bh * 512 + j0;
        __syncthreads();
        {
            float4 k0 = *(const float4*)&g_km[(tokJ + sj) * 32 + sgrp * 8];
            float4 k1 = *(const float4*)&g_km[(tokJ + sj) * 32 + sgrp * 8 + 4];
            #pragma unroll
            for (int t = 0; t < 4; t++)
                sKm[(sgrp * 8 + t) * KM_STR + sj] = spl(((const float*)&k0)[t]);
            #pragma unroll
            for (int t = 0; t < 4; t++)
                sKm[(sgrp * 8 + 4 + t) * KM_STR + sj] = spl(((const float*)&k1)[t]);
            #pragma unroll
            for (int q4 = 0; q4 < 4; q4++) {
                float4 vv = *(const float4*)&g_v[(tokJ + sj) * 64 + sgrp * 16 + q4 * 4];
                #pragma unroll
                for (int t = 0; t < 4; t++)
                    sV[sj * V_STR + sgrp * 16 + q4 * 4 + t] = spl(((const float*)&vv)[t]);
            }
            if (tid < 64) sK2[tid] = g_k2[tokJ + tid];
        }
        __syncthreads();

        #pragma unroll
        for (int nt = 0; nt < 8; nt++) {
            float cqk[4] = {0.f, 0.f, 0.f, 0.f};
            float cu0[4] = {0.f, 0.f, 0.f, 0.f};
            float cu1[4] = {0.f, 0.f, 0.f, 0.f};
            float cu2[4] = {0.f, 0.f, 0.f, 0.f};
            float cu3[4] = {0.f, 0.f, 0.f, 0.f};
            #pragma unroll
            for (int kk = 0; kk < 4; kk++) {
                uint2 b0 = sKm[(kk * 8 + tg) * KM_STR + nt * 8 + g];
                uint2 b1 = sKm[(kk * 8 + tg + 4) * KM_STR + nt * 8 + g];
                mma8(cqk, mm[kk][0].x, mm[kk][1].x, mm[kk][2].x, mm[kk][3].x, b0.x, b1.x);
                mma8(cqk, mm[kk][0].x, mm[kk][1].x, mm[kk][2].x, mm[kk][3].x, b0.y, b1.y);
                mma8(cqk, mm[kk][0].y, mm[kk][1].y, mm[kk][2].y, mm[kk][3].y, b0.x, b1.x);
                mma8(cu0, uf[0][kk][0], uf[0][kk][1], uf[0][kk][2], uf[0][kk][3], b0.x, b1.x);
                mma8(cu1, uf[1][kk][0], uf[1][kk][1], uf[1][kk][2], uf[1][kk][3], b0.x, b1.x);
                mma8(cu2, uf[2][kk][0], uf[2][kk][1], uf[2][kk][2], uf[2][kk][3], b0.x, b1.x);
                mma8(cu3, uf[3][kk][0], uf[3][kk][1], uf[3][kk][2], uf[3][kk][3], b0.x, b1.x);
            }
            int colA = nt * 8 + 2 * tg;
            float2 k2p = *(const float2*)&sK2[colA];
            int jRelA = j0 + colA, jRelB = jRelA + 1;
            float p[4];
            #pragma unroll
            for (int e = 0; e < 4; e++) {
                float cival = (e < 2) ? ci0 : ci1;
                float k2v   = (e & 1) ? k2p.y : k2p.x;
                float dist = cival + k2v - 2.f * cqk[e]
                           + cu0[e] * cu0[e] + cu1[e] * cu1[e]
                           + cu2[e] * cu2[e] + cu3[e] * cu3[e];
                p[e] = __expf(-fmaxf(dist, 0.f) * invT);
            }
            if (jRelA > iRelA) p[0] = 0.f;
            if (jRelB > iRelA) p[1] = 0.f;
            if (jRelA > iRelB) p[2] = 0.f;
            if (jRelB > iRelB) p[3] = 0.f;
            runs0 += p[0] + p[1];
            runs1 += p[2] + p[3];
            uint2 s0 = spl(p[0]), s1 = spl(p[1]);
            uint2 s2 = spl(p[2]), s3 = spl(p[3]);
            *(uint4*)&sP[(r0w + g) * P_STR + colA]     = make_uint4(s0.x, s0.y, s1.x, s1.y);
            *(uint4*)&sP[(r0w + g + 8) * P_STR + colA] = make_uint4(s2.x, s2.y, s3.x, s3.y);
        }
        __syncwarp();

        #pragma unroll
        for (int kk = 0; kk < 8; kk++) {
            uint2 A0 = sP[(r0w + g) * P_STR + kk * 8 + tg];
            uint2 A1 = sP[(r0w + g + 8) * P_STR + kk * 8 + tg];
            uint2 A2 = sP[(r0w + g) * P_STR + kk * 8 + tg + 4];
            uint2 A3 = sP[(r0w + g + 8) * P_STR + kk * 8 + tg + 4];
            #pragma unroll
            for (int nt = 0; nt < 8; nt++) {
                uint2 b0 = sV[(kk * 8 + tg) * V_STR + nt * 8 + g];
                uint2 b1 = sV[(kk * 8 + tg + 4) * V_STR + nt * 8 + g];
                mma8(cpv[nt], A0.x, A1.x, A2.x, A3.x, b0.x, b1.x);
                mma8(cpv[nt], A0.x, A1.x, A2.x, A3.x, b0.y, b1.y);
                mma8(cpv[nt], A0.y, A1.y, A2.y, A3.y, b0.x, b1.x);
            }
        }
    }

    const unsigned FULL = 0xffffffffu;
    float s0 = runs0, s1 = runs1;
    s0 += __shfl_xor_sync(FULL, s0, 1); s0 += __shfl_xor_sync(FULL, s0, 2);
    s1 += __shfl_xor_sync(FULL, s1, 1); s1 += __shfl_xor_sync(FULL, s1, 2);
    if (tg == 0) {
        g_psum[jc][rA] = s0;
        g_psum[jc][rB] = s1;
    }
    #pragma unroll
    for (int nt = 0; nt < 8; nt++) {
        int col = nt * 8 + 2 * tg;
        *(float2*)&g_pacc[jc][(size_t)rA * 64 + col] = make_float2(cpv[nt][0], cpv[nt][1]);
        *(float2*)&g_pacc[jc][(size_t)rB * 64 + col] = make_float2(cpv[nt][2], cpv[nt][3]);
    }
}

// ---------------- merge partials -> g_ao -------------------------------------
__global__ void merge_kernel()
{
    int idx = blockIdx.x * 256 + threadIdx.x;
    int tok = idx >> 4, c4 = idx & 15;
    int i = tok & 511;
    float4 a = *(const float4*)&g_pacc[0][tok * 64 + c4 * 4];
    float s = g_psum[0][tok];
    int iq = i & 127;
    if (iq >= 64 || i >= 128) {
        float4 b = *(const float4*)&g_pacc[1][tok * 64 + c4 * 4];
        a.x += b.x; a.y += b.y; a.z += b.z; a.w += b.w;
        s += g_psum[1][tok];
    }
    float inv = 1.f / s;
    int bh = tok >> 9;
    int b = bh >> 4, h = bh & 15;
    float4 o = make_float4(a.x * inv, a.y * inv, a.z * inv, a.w * inv);
    *(float4*)&g_ao[(b * 512 + i) * 1024 + h * 64 + c4 * 4] = o;
}

// ---------------- launch ------------------------------------------------------
extern "C" void kernel_launch(void* const* d_in, const int* in_sizes, int n_in,
                              void* d_out, int out_size)
{
    const float* x    = (const float*)d_in[0];
    const float* Wq   = (const float*)d_in[1];
    const float* Wk   = (const float*)d_in[2];
    const float* Wv   = (const float*)d_in[3];
    const float* Wo   = (const float*)d_in[4];
    const float* Wqm  = (const float*)d_in[5];
    const float* Wkm  = (const float*)d_in[6];
    const float* Wmet = (const float*)d_in[7];
    const float* temp = (const float*)d_in[8];
    float*       out  = (float*)d_out;

    cudaFuncSetAttribute(gemm_tc,
                         cudaFuncAttributeMaxDynamicSharedMemorySize, GEMM_SMEM);
    cudaFuncSetAttribute(attn_mma,
                         cudaFuncAttributeMaxDynamicSharedMemorySize, ATTN_SMEM);

    uint2 *xs;
    cudaGetSymbolAddress((void**)&xs, g_xs);

    splitA<<<512, 256>>>(x, xs);
    splitW4<<<2048, 256>>>(Wq, Wk, Wv, Wo);

    gemm_tc<<<dim3(8, 8, 3), 256, GEMM_SMEM>>>(nullptr, 0);
    rope_kernel<<<(BHT * 32) / 256, 256>>>();
    metric_kernel<<<BHT / 8, 256>>>(Wqm, Wkm, Wmet);
    attn_mma<<<dim3(8, Bb * Hh), 256, ATTN_SMEM>>>(temp);
    merge_kernel<<<1024, 256>>>();

    float* ao;
    cudaGetSymbolAddress((void**)&ao, g_ao);
    splitA<<<512, 256>>>(ao, xs);
    gemm_tc<<<dim3(8, 8, 1), 256, GEMM_SMEM>>>(out, 1);
}

// round 12
// speedup vs baseline: 1.2753x; 1.2753x over previous
#include <cuda_runtime.h>
#include <math.h>

#define Bb   2
#define Tt   512
#define Hh   16
#define BHT  16384
#define MSZ  (1024*1024)

// ---------------- scratch ----------------------------------------------------
__device__ float g_q [BHT*64];
__device__ float g_k [BHT*64];
__device__ float g_v [BHT*64];
__device__ float g_km[BHT*32];
__device__ float g_k2[BHT];
__device__ float g_U [BHT*128];
__device__ float g_m [BHT*32];
__device__ float g_c [BHT];
__device__ float g_pacc[2][BHT*64];
__device__ float g_psum[2][BHT];
__device__ float g_ao[Bb*Tt*1024];
// bf16 split-packed operands: uint2 = (ah_pair, al_pair) per 2 k-elements
__device__ uint2 g_xs[MSZ/2];        // A  [1024 rows][512 kp]
__device__ uint2 g_ws[4*(MSZ/2)];    // W  [512 kp][1024 n] x4

// ---------------- bf16 split helpers -------------------------------------------
__device__ __forceinline__ uint2 sbf(float a, float b) {
    unsigned ph;
    asm("cvt.rn.bf16x2.f32 %0,%1,%2;" : "=r"(ph) : "f"(b), "f"(a));
    float ra = a - __uint_as_float(ph << 16);
    float rb = b - __uint_as_float(ph & 0xffff0000u);
    unsigned pl;
    asm("cvt.rn.bf16x2.f32 %0,%1,%2;" : "=r"(pl) : "f"(rb), "f"(ra));
    return make_uint2(ph, pl);
}

// ---------------- tf32 helpers (attention only) --------------------------------
__device__ __forceinline__ unsigned tf32of(float x) {
    unsigned r; asm("cvt.rna.tf32.f32 %0,%1;" : "=r"(r) : "f"(x)); return r;
}
__device__ __forceinline__ uint2 spl(float x) {
    unsigned h = tf32of(x);
    unsigned l = tf32of(x - __uint_as_float(h));
    return make_uint2(h, l);
}
__device__ __forceinline__ void mma8(float* c,
    unsigned a0, unsigned a1, unsigned a2, unsigned a3,
    unsigned b0, unsigned b1)
{
    asm volatile(
        "mma.sync.aligned.m16n8k8.row.col.f32.tf32.tf32.f32 "
        "{%0,%1,%2,%3},{%4,%5,%6,%7},{%8,%9},{%0,%1,%2,%3};"
        : "+f"(c[0]), "+f"(c[1]), "+f"(c[2]), "+f"(c[3])
        : "r"(a0), "r"(a1), "r"(a2), "r"(a3), "r"(b0), "r"(b1));
}
__device__ __forceinline__ void mma16(float* c,
    unsigned a0, unsigned a1, unsigned a2, unsigned a3,
    unsigned b0, unsigned b1)
{
    asm volatile(
        "mma.sync.aligned.m16n8k16.row.col.f32.bf16.bf16.f32 "
        "{%0,%1,%2,%3},{%4,%5,%6,%7},{%8,%9},{%0,%1,%2,%3};"
        : "+f"(c[0]), "+f"(c[1]), "+f"(c[2]), "+f"(c[3])
        : "r"(a0), "r"(a1), "r"(a2), "r"(a3), "r"(b0), "r"(b1));
}

// ---------------- split kernels -------------------------------------------------
__global__ void splitA(const float* __restrict__ src, uint2* __restrict__ dst)
{
    int idx = blockIdx.x * 256 + threadIdx.x;
    float4 v0 = *(const float4*)&src[idx * 8];
    float4 v1 = *(const float4*)&src[idx * 8 + 4];
    dst[idx * 4 + 0] = sbf(v0.x, v0.y);
    dst[idx * 4 + 1] = sbf(v0.z, v0.w);
    dst[idx * 4 + 2] = sbf(v1.x, v1.y);
    dst[idx * 4 + 3] = sbf(v1.z, v1.w);
}

// fused: all 4 weights in one launch (blockIdx.x >> 9 selects matrix)
__global__ void splitW4(const float* __restrict__ W0, const float* __restrict__ W1,
                        const float* __restrict__ W2, const float* __restrict__ W3)
{
    int m = blockIdx.x >> 9;
    const float* W = (m == 0) ? W0 : (m == 1) ? W1 : (m == 2) ? W2 : W3;
    uint2* dst = g_ws + m * (MSZ / 2);
    int idx = (blockIdx.x & 511) * 256 + threadIdx.x;
    int kp = idx >> 8;
    int n4 = (idx & 255) * 4;
    float4 r0 = *(const float4*)&W[(2 * kp) * 1024 + n4];
    float4 r1 = *(const float4*)&W[(2 * kp + 1) * 1024 + n4];
    dst[kp * 1024 + n4 + 0] = sbf(r0.x, r1.x);
    dst[kp * 1024 + n4 + 1] = sbf(r0.y, r1.y);
    dst[kp * 1024 + n4 + 2] = sbf(r0.z, r1.z);
    dst[kp * 1024 + n4 + 3] = sbf(r0.w, r1.w);
}

// ---------------- GEMM (3x bf16, R10 tiling + double-buffered smem) ------------
// mode 0: A = g_xs (x), W = g_ws + z*(MSZ/2), head-split store
// mode 1: A = g_xs (ao re-split), W = g_ws + 3*(MSZ/2), plain store to Cout
#define SA_STR 18
#define SB_STR 68
#define BUF_SZ (128*SA_STR + 16*SB_STR)
#define GEMM_SMEM (2 * BUF_SZ * 8)

__global__ void __launch_bounds__(256) gemm_tc(float* __restrict__ Cout, int mode)
{
    extern __shared__ uint2 sm2[];

    int z = blockIdx.z;
    const uint4* Wm = (const uint4*)(g_ws + (mode == 0 ? z : 3) * (MSZ/2));
    const uint4* Am = (const uint4*)g_xs;

    int tid  = threadIdx.x;
    int lane = tid & 31;
    int wid  = tid >> 5;
    int wm   = wid & 3;
    int wn   = wid >> 2;
    int g    = lane >> 2;
    int tg   = lane & 3;
    int row0 = blockIdx.y * 128;
    int col0 = blockIdx.x * 64;

    // A tile: 128 rows x 8 uint4 (16 kp) -> 4 per thread
    int aRow[4], aK4[4], sAi[4];
    #pragma unroll
    for (int e = 0; e < 4; e++) {
        int idx = tid + e * 256;
        aRow[e] = idx >> 3; aK4[e] = idx & 7;
        sAi[e]  = aRow[e] * SA_STR + aK4[e] * 2;
    }
    // B tile: 16 kp x 32 uint4 (64 cols) -> 2 uint4 per thread
    int bKp = tid >> 4, bC4 = tid & 15;
    int sBi = 128 * SA_STR + bKp * SB_STR + bC4 * 4;
    int bGi = bKp * 512 + col0 / 2 + bC4 * 2;

    float acc[2][4][4];
    #pragma unroll
    for (int mt = 0; mt < 2; mt++)
        #pragma unroll
        for (int nt = 0; nt < 4; nt++)
            #pragma unroll
            for (int e = 0; e < 4; e++) acc[mt][nt][e] = 0.f;

    uint4 av[4], bv0, bv1;
    #pragma unroll
    for (int e = 0; e < 4; e++)
        av[e] = Am[(row0 + aRow[e]) * 256 + aK4[e]];
    bv0 = Wm[bGi];
    bv1 = Wm[bGi + 1];

    // store tile 0 into buffer 0
    {
        uint2* buf = sm2;
        #pragma unroll
        for (int e = 0; e < 4; e++)
            *(uint4*)&buf[sAi[e]] = av[e];
        *(uint4*)&buf[sBi]     = bv0;
        *(uint4*)&buf[sBi + 2] = bv1;
    }
    __syncthreads();

    for (int t = 0; t < 32; t++) {
        uint2* cur = sm2 + (t & 1) * BUF_SZ;
        uint2* nxt = sm2 + ((t & 1) ^ 1) * BUF_SZ;

        // prefetch tile t+1 (global) before MMAs so latency hides under them
        if (t < 31) {
            #pragma unroll
            for (int e = 0; e < 4; e++)
                av[e] = Am[(row0 + aRow[e]) * 256 + (t + 1) * 8 + aK4[e]];
            bv0 = Wm[(t + 1) * 16 * 512 + bGi];
            bv1 = Wm[(t + 1) * 16 * 512 + bGi + 1];
        }

        #pragma unroll
        for (int ks = 0; ks < 2; ks++) {
            uint2 Afr[2][4];
            #pragma unroll
            for (int mt = 0; mt < 2; mt++) {
                int rb = (wm * 32 + mt * 16 + g) * SA_STR + ks * 8 + tg;
                Afr[mt][0] = cur[rb];
                Afr[mt][2] = cur[rb + 4];
                Afr[mt][1] = cur[rb + 8 * SA_STR];
                Afr[mt][3] = cur[rb + 8 * SA_STR + 4];
            }
            #pragma unroll
            for (int nt = 0; nt < 4; nt++) {
                int cb = 128 * SA_STR + (ks * 8 + tg) * SB_STR + wn * 32 + nt * 8 + g;
                uint2 B0 = cur[cb];
                uint2 B1 = cur[cb + 4 * SB_STR];
                #pragma unroll
                for (int mt = 0; mt < 2; mt++) {
                    float* c = acc[mt][nt];
                    mma16(c, Afr[mt][0].x, Afr[mt][1].x, Afr[mt][2].x, Afr[mt][3].x,
                          B0.x, B1.x);                               // hi*hi
                    mma16(c, Afr[mt][0].x, Afr[mt][1].x, Afr[mt][2].x, Afr[mt][3].x,
                          B0.y, B1.y);                               // hi*lo
                    mma16(c, Afr[mt][0].y, Afr[mt][1].y, Afr[mt][2].y, Afr[mt][3].y,
                          B0.x, B1.x);                               // lo*hi
                }
            }
        }

        // store tile t+1 into the other buffer (no one reads it this iter)
        if (t < 31) {
            #pragma unroll
            for (int e = 0; e < 4; e++)
                *(uint4*)&nxt[sAi[e]] = av[e];
            *(uint4*)&nxt[sBi]     = bv0;
            *(uint4*)&nxt[sBi + 2] = bv1;
        }
        __syncthreads();
    }

    if (mode == 1) {
        #pragma unroll
        for (int mt = 0; mt < 2; mt++) {
            int row = row0 + wm * 32 + mt * 16 + g;
            #pragma unroll
            for (int nt = 0; nt < 4; nt++) {
                int col = col0 + wn * 32 + nt * 8 + 2 * tg;
                *(float2*)&Cout[row * 1024 + col] =
                    make_float2(acc[mt][nt][0], acc[mt][nt][1]);
                *(float2*)&Cout[(row + 8) * 1024 + col] =
                    make_float2(acc[mt][nt][2], acc[mt][nt][3]);
            }
        }
    } else {
        float* dst = (z == 0) ? g_q : (z == 1) ? g_k : g_v;
        int h = blockIdx.x;
        #pragma unroll
        for (int mt = 0; mt < 2; mt++) {
            int row = row0 + wm * 32 + mt * 16 + g;
            int b0r = row >> 9, t0r = row & 511;
            int b1r = (row + 8) >> 9, t1r = (row + 8) & 511;
            #pragma unroll
            for (int nt = 0; nt < 4; nt++) {
                int col = wn * 32 + nt * 8 + 2 * tg;
                *(float2*)&dst[(((b0r << 4) + h) * 512 + t0r) * 64 + col] =
                    make_float2(acc[mt][nt][0], acc[mt][nt][1]);
                *(float2*)&dst[(((b1r << 4) + h) * 512 + t1r) * 64 + col] =
                    make_float2(acc[mt][nt][2], acc[mt][nt][3]);
            }
        }
    }
}

// ---------------- RoPE (in place on g_q, g_k) -------------------------------
__global__ void rope_kernel()
{
    int idx = blockIdx.x * blockDim.x + threadIdx.x;
    if (idx >= BHT * 32) return;
    int tok = idx >> 5;
    int j   = idx & 31;
    int t   = tok & 511;
    float inv = expf(-((float)(2 * j) / 64.0f) * 9.210340371976184f);
    float fr  = (float)t * inv;
    float s, c;
    sincosf(fr, &s, &c);

    float* q = g_q + tok * 64;
    float x1 = q[j], x2 = q[j + 32];
    q[j]      = x1 * c - x2 * s;
    q[j + 32] = x1 * s + x2 * c;

    float* k = g_k + tok * 64;
    x1 = k[j]; x2 = k[j + 32];
    k[j]      = x1 * c - x2 * s;
    k[j + 32] = x1 * s + x2 * c;
}

// ---------------- metric (R4): km, k2, U, m = qm+w, c = q2+|Uq|^2 ------------
__global__ void __launch_bounds__(256) metric_kernel(
    const float* __restrict__ Wqm, const float* __restrict__ Wkm,
    const float* __restrict__ Wmetric)
{
    __shared__ float sWqm[64 * 32];
    __shared__ float sWkm[64 * 32];
    __shared__ float sWm [32 * 128];
    int tid = threadIdx.x;
    for (int i = tid; i < 64 * 32; i += 256) { sWqm[i] = Wqm[i]; sWkm[i] = Wkm[i]; }
    for (int i = tid; i < 32 * 128; i += 256) { sWm[i] = Wmetric[i]; }
    __syncthreads();

    const unsigned FULL = 0xffffffffu;
    int w = tid >> 5, lane = tid & 31;
    int tok = blockIdx.x * 8 + w;

    const float* q = g_q + tok * 64;
    const float* k = g_k + tok * 64;
    float a0 = q[lane], a1 = q[lane + 32];
    float b0 = k[lane], b1 = k[lane + 32];

    float accq = 0.f, acck = 0.f;
    #pragma unroll
    for (int d = 0; d < 32; d++) {
        float qd = __shfl_sync(FULL, a0, d);
        float kd = __shfl_sync(FULL, b0, d);
        accq += qd * sWqm[d * 32 + lane];
        acck += kd * sWkm[d * 32 + lane];
    }
    #pragma unroll
    for (int d = 0; d < 32; d++) {
        float qd = __shfl_sync(FULL, a1, d);
        float kd = __shfl_sync(FULL, b1, d);
        accq += qd * sWqm[(d + 32) * 32 + lane];
        acck += kd * sWkm[(d + 32) * 32 + lane];
    }
    float qmv = 1.f / (1.f + expf(-accq));
    float kmv = 1.f / (1.f + expf(-acck));
    g_km[tok * 32 + lane] = kmv;

    float q2 = qmv * qmv, k2 = kmv * kmv;
    #pragma unroll
    for (int o = 16; o > 0; o >>= 1) {
        q2 += __shfl_xor_sync(FULL, q2, o);
        k2 += __shfl_xor_sync(FULL, k2, o);
    }
    if (lane == 0) g_k2[tok] = k2;

    float u0 = 0.f, u1 = 0.f, u2 = 0.f, u3 = 0.f;
    #pragma unroll
    for (int d = 0; d < 32; d++) {
        float qd = __shfl_sync(FULL, qmv, d);
        float4 wv = *(const float4*)&sWm[d * 128 + lane * 4];
        u0 += qd * wv.x; u1 += qd * wv.y; u2 += qd * wv.z; u3 += qd * wv.w;
    }
    *(float4*)&g_U[tok * 128 + lane * 4] = make_float4(u0, u1, u2, u3);

    float p0 = u0 * qmv, p1 = u1 * qmv, p2 = u2 * qmv, p3 = u3 * qmv;
    #pragma unroll
    for (int o = 16; o > 0; o >>= 1) {
        p0 += __shfl_xor_sync(FULL, p0, o);
        p1 += __shfl_xor_sync(FULL, p1, o);
        p2 += __shfl_xor_sync(FULL, p2, o);
        p3 += __shfl_xor_sync(FULL, p3, o);
    }
    float wd = p0 * u0 + p1 * u1 + p2 * u2 + p3 * u3;
    g_m[tok * 32 + lane] = qmv + wd;
    if (lane == 0)
        g_c[tok] = q2 + p0 * p0 + p1 * p1 + p2 * p2 + p3 * p3;
}

// ---------------- attention via MMA (R7, frozen) -------------------------------
#define KM_STR 66
#define V_STR  66
#define P_STR  66
#define ATTN_SMEM ((32*KM_STR + 64*V_STR + 128*P_STR) * 8 + 64 * 4)

__global__ void __launch_bounds__(256) attn_mma(const float* __restrict__ temp_ptr)
{
    extern __shared__ uint2 smem[];
    uint2* sKm = smem;
    uint2* sV  = sKm + 32 * KM_STR;
    uint2* sP  = sV + 64 * V_STR;
    float* sK2 = (float*)(sP + 128 * P_STR);

    int qt = 3 - (int)(blockIdx.x >> 1);
    int jc = blockIdx.x & 1;
    int bh = blockIdx.y;
    int tok0 = bh * 512 + qt * 128;

    int tid  = threadIdx.x;
    int lane = tid & 31;
    int wid  = tid >> 5;
    int g    = lane >> 2;
    int tg   = lane & 3;
    int r0w  = wid * 16;

    float invT = 1.0f / fmaxf(temp_ptr[0], 0.5f);

    int rA = tok0 + r0w + g;
    int rB = rA + 8;
    int iRelA = qt * 128 + r0w + g;
    int iRelB = iRelA + 8;

    uint2 mm[4][4];
    unsigned uf[4][4][4];
    #pragma unroll
    for (int kk = 0; kk < 4; kk++) {
        int d0 = kk * 8 + tg;
        mm[kk][0] = spl(g_m[rA * 32 + d0]);
        mm[kk][1] = spl(g_m[rB * 32 + d0]);
        mm[kk][2] = spl(g_m[rA * 32 + d0 + 4]);
        mm[kk][3] = spl(g_m[rB * 32 + d0 + 4]);
        float4 uA0 = *(const float4*)&g_U[rA * 128 + d0 * 4];
        float4 uB0 = *(const float4*)&g_U[rB * 128 + d0 * 4];
        float4 uA4 = *(const float4*)&g_U[rA * 128 + (d0 + 4) * 4];
        float4 uB4 = *(const float4*)&g_U[rB * 128 + (d0 + 4) * 4];
        #pragma unroll
        for (int r = 0; r < 4; r++) {
            uf[r][kk][0] = tf32of(((const float*)&uA0)[r]);
            uf[r][kk][1] = tf32of(((const float*)&uB0)[r]);
            uf[r][kk][2] = tf32of(((const float*)&uA4)[r]);
            uf[r][kk][3] = tf32of(((const float*)&uB4)[r]);
        }
    }
    float ci0 = g_c[rA], ci1 = g_c[rB];

    float cpv[8][4];
    #pragma unroll
    for (int nt = 0; nt < 8; nt++)
        #pragma unroll
        for (int e = 0; e < 4; e++) cpv[nt][e] = 0.f;
    float runs0 = 0.f, runs1 = 0.f;

    int sj   = tid >> 2;
    int sgrp = tid & 3;

    for (int jt = jc; jt <= 2 * qt + 1; jt += 2) {
        int j0 = jt * 64;
        int tokJ = bh * 512 + j0;
        __syncthreads();
        {
            float4 k0 = *(const float4*)&g_km[(tokJ + sj) * 32 + sgrp * 8];
            float4 k1 = *(const float4*)&g_km[(tokJ + sj) * 32 + sgrp * 8 + 4];
            #pragma unroll
            for (int t = 0; t < 4; t++)
                sKm[(sgrp * 8 + t) * KM_STR + sj] = spl(((const float*)&k0)[t]);
            #pragma unroll
            for (int t = 0; t < 4; t++)
                sKm[(sgrp * 8 + 4 + t) * KM_STR + sj] = spl(((const float*)&k1)[t]);
            #pragma unroll
            for (int q4 = 0; q4 < 4; q4++) {
                float4 vv = *(const float4*)&g_v[(tokJ + sj) * 64 + sgrp * 16 + q4 * 4];
                #pragma unroll
                for (int t = 0; t < 4; t++)
                    sV[sj * V_STR + sgrp * 16 + q4 * 4 + t] = spl(((const float*)&vv)[t]);
            }
            if (tid < 64) sK2[tid] = g_k2[tokJ + tid];
        }
        __syncthreads();

        #pragma unroll
        for (int nt = 0; nt < 8; nt++) {
            float cqk[4] = {0.f, 0.f, 0.f, 0.f};
            float cu0[4] = {0.f, 0.f, 0.f, 0.f};
            float cu1[4] = {0.f, 0.f, 0.f, 0.f};
            float cu2[4] = {0.f, 0.f, 0.f, 0.f};
            float cu3[4] = {0.f, 0.f, 0.f, 0.f};
            #pragma unroll
            for (int kk = 0; kk < 4; kk++) {
                uint2 b0 = sKm[(kk * 8 + tg) * KM_STR + nt * 8 + g];
                uint2 b1 = sKm[(kk * 8 + tg + 4) * KM_STR + nt * 8 + g];
                mma8(cqk, mm[kk][0].x, mm[kk][1].x, mm[kk][2].x, mm[kk][3].x, b0.x, b1.x);
                mma8(cqk, mm[kk][0].x, mm[kk][1].x, mm[kk][2].x, mm[kk][3].x, b0.y, b1.y);
                mma8(cqk, mm[kk][0].y, mm[kk][1].y, mm[kk][2].y, mm[kk][3].y, b0.x, b1.x);
                mma8(cu0, uf[0][kk][0], uf[0][kk][1], uf[0][kk][2], uf[0][kk][3], b0.x, b1.x);
                mma8(cu1, uf[1][kk][0], uf[1][kk][1], uf[1][kk][2], uf[1][kk][3], b0.x, b1.x);
                mma8(cu2, uf[2][kk][0], uf[2][kk][1], uf[2][kk][2], uf[2][kk][3], b0.x, b1.x);
                mma8(cu3, uf[3][kk][0], uf[3][kk][1], uf[3][kk][2], uf[3][kk][3], b0.x, b1.x);
            }
            int colA = nt * 8 + 2 * tg;
            float2 k2p = *(const float2*)&sK2[colA];
            int jRelA = j0 + colA, jRelB = jRelA + 1;
            float p[4];
            #pragma unroll
            for (int e = 0; e < 4; e++) {
                float cival = (e < 2) ? ci0 : ci1;
                float k2v   = (e & 1) ? k2p.y : k2p.x;
                float dist = cival + k2v - 2.f * cqk[e]
                           + cu0[e] * cu0[e] + cu1[e] * cu1[e]
                           + cu2[e] * cu2[e] + cu3[e] * cu3[e];
                p[e] = __expf(-fmaxf(dist, 0.f) * invT);
            }
            if (jRelA > iRelA) p[0] = 0.f;
            if (jRelB > iRelA) p[1] = 0.f;
            if (jRelA > iRelB) p[2] = 0.f;
            if (jRelB > iRelB) p[3] = 0.f;
            runs0 += p[0] + p[1];
            runs1 += p[2] + p[3];
            uint2 s0 = spl(p[0]), s1 = spl(p[1]);
            uint2 s2 = spl(p[2]), s3 = spl(p[3]);
            *(uint4*)&sP[(r0w + g) * P_STR + colA]     = make_uint4(s0.x, s0.y, s1.x, s1.y);
            *(uint4*)&sP[(r0w + g + 8) * P_STR + colA] = make_uint4(s2.x, s2.y, s3.x, s3.y);
        }
        __syncwarp();

        #pragma unroll
        for (int kk = 0; kk < 8; kk++) {
            uint2 A0 = sP[(r0w + g) * P_STR + kk * 8 + tg];
            uint2 A1 = sP[(r0w + g + 8) * P_STR + kk * 8 + tg];
            uint2 A2 = sP[(r0w + g) * P_STR + kk * 8 + tg + 4];
            uint2 A3 = sP[(r0w + g + 8) * P_STR + kk * 8 + tg + 4];
            #pragma unroll
            for (int nt = 0; nt < 8; nt++) {
                uint2 b0 = sV[(kk * 8 + tg) * V_STR + nt * 8 + g];
                uint2 b1 = sV[(kk * 8 + tg + 4) * V_STR + nt * 8 + g];
                mma8(cpv[nt], A0.x, A1.x, A2.x, A3.x, b0.x, b1.x);
                mma8(cpv[nt], A0.x, A1.x, A2.x, A3.x, b0.y, b1.y);
                mma8(cpv[nt], A0.y, A1.y, A2.y, A3.y, b0.x, b1.x);
            }
        }
    }

    const unsigned FULL = 0xffffffffu;
    float s0 = runs0, s1 = runs1;
    s0 += __shfl_xor_sync(FULL, s0, 1); s0 += __shfl_xor_sync(FULL, s0, 2);
    s1 += __shfl_xor_sync(FULL, s1, 1); s1 += __shfl_xor_sync(FULL, s1, 2);
    if (tg == 0) {
        g_psum[jc][rA] = s0;
        g_psum[jc][rB] = s1;
    }
    #pragma unroll
    for (int nt = 0; nt < 8; nt++) {
        int col = nt * 8 + 2 * tg;
        *(float2*)&g_pacc[jc][(size_t)rA * 64 + col] = make_float2(cpv[nt][0], cpv[nt][1]);
        *(float2*)&g_pacc[jc][(size_t)rB * 64 + col] = make_float2(cpv[nt][2], cpv[nt][3]);
    }
}

// ---------------- merge partials -> g_ao -------------------------------------
__global__ void merge_kernel()
{
    int idx = blockIdx.x * 256 + threadIdx.x;
    int tok = idx >> 4, c4 = idx & 15;
    int i = tok & 511;
    float4 a = *(const float4*)&g_pacc[0][tok * 64 + c4 * 4];
    float s = g_psum[0][tok];
    int iq = i & 127;
    if (iq >= 64 || i >= 128) {
        float4 b = *(const float4*)&g_pacc[1][tok * 64 + c4 * 4];
        a.x += b.x; a.y += b.y; a.z += b.z; a.w += b.w;
        s += g_psum[1][tok];
    }
    float inv = 1.f / s;
    int bh = tok >> 9;
    int b = bh >> 4, h = bh & 15;
    float4 o = make_float4(a.x * inv, a.y * inv, a.z * inv, a.w * inv);
    *(float4*)&g_ao[(b * 512 + i) * 1024 + h * 64 + c4 * 4] = o;
}

// ---------------- launch ------------------------------------------------------
extern "C" void kernel_launch(void* const* d_in, const int* in_sizes, int n_in,
                              void* d_out, int out_size)
{
    const float* x    = (const float*)d_in[0];
    const float* Wq   = (const float*)d_in[1];
    const float* Wk   = (const float*)d_in[2];
    const float* Wv   = (const float*)d_in[3];
    const float* Wo   = (const float*)d_in[4];
    const float* Wqm  = (const float*)d_in[5];
    const float* Wkm  = (const float*)d_in[6];
    const float* Wmet = (const float*)d_in[7];
    const float* temp = (const float*)d_in[8];
    float*       out  = (float*)d_out;

    cudaFuncSetAttribute(gemm_tc,
                         cudaFuncAttributeMaxDynamicSharedMemorySize, GEMM_SMEM);
    cudaFuncSetAttribute(attn_mma,
                         cudaFuncAttributeMaxDynamicSharedMemorySize, ATTN_SMEM);

    uint2 *xs;
    cudaGetSymbolAddress((void**)&xs, g_xs);

    splitA<<<512, 256>>>(x, xs);
    splitW4<<<2048, 256>>>(Wq, Wk, Wv, Wo);

    gemm_tc<<<dim3(16, 8, 3), 256, GEMM_SMEM>>>(nullptr, 0);
    rope_kernel<<<(BHT * 32) / 256, 256>>>();
    metric_kernel<<<BHT / 8, 256>>>(Wqm, Wkm, Wmet);
    attn_mma<<<dim3(8, Bb * Hh), 256, ATTN_SMEM>>>(temp);
    merge_kernel<<<1024, 256>>>();

    float* ao;
    cudaGetSymbolAddress((void**)&ao, g_ao);
    splitA<<<512, 256>>>(ao, xs);
    gemm_tc<<<dim3(16, 8, 1), 256, GEMM_SMEM>>>(out, 1);
}

// round 13
// speedup vs baseline: 1.3554x; 1.0628x over previous
#include <cuda_runtime.h>
#include <math.h>

#define Bb   2
#define Tt   512
#define Hh   16
#define BHT  16384
#define MSZ  (1024*1024)

// ---------------- scratch ----------------------------------------------------
__device__ float g_q [BHT*64];
__device__ float g_k [BHT*64];
__device__ float g_v [BHT*64];
__device__ float g_km[BHT*32];
__device__ float g_k2[BHT];
__device__ float g_U [BHT*128];
__device__ float g_m [BHT*32];
__device__ float g_c [BHT];
__device__ float g_pacc[2][BHT*64];
__device__ float g_psum[2][BHT];
__device__ float g_ao[Bb*Tt*1024];
// bf16 split-packed operands: uint2 = (ah_pair, al_pair) per 2 k-elements
__device__ uint2 g_xs[MSZ/2];        // A  [1024 rows][512 kp]
__device__ uint2 g_ws[4*(MSZ/2)];    // W  [512 kp][1024 n] x4

// ---------------- bf16 split helpers -------------------------------------------
__device__ __forceinline__ uint2 sbf(float a, float b) {
    unsigned ph;
    asm("cvt.rn.bf16x2.f32 %0,%1,%2;" : "=r"(ph) : "f"(b), "f"(a));
    float ra = a - __uint_as_float(ph << 16);
    float rb = b - __uint_as_float(ph & 0xffff0000u);
    unsigned pl;
    asm("cvt.rn.bf16x2.f32 %0,%1,%2;" : "=r"(pl) : "f"(rb), "f"(ra));
    return make_uint2(ph, pl);
}

// ---------------- tf32 helpers (attention scores) -------------------------------
__device__ __forceinline__ unsigned tf32of(float x) {
    unsigned r; asm("cvt.rna.tf32.f32 %0,%1;" : "=r"(r) : "f"(x)); return r;
}
__device__ __forceinline__ uint2 spl(float x) {
    unsigned h = tf32of(x);
    unsigned l = tf32of(x - __uint_as_float(h));
    return make_uint2(h, l);
}
__device__ __forceinline__ void mma8(float* c,
    unsigned a0, unsigned a1, unsigned a2, unsigned a3,
    unsigned b0, unsigned b1)
{
    asm volatile(
        "mma.sync.aligned.m16n8k8.row.col.f32.tf32.tf32.f32 "
        "{%0,%1,%2,%3},{%4,%5,%6,%7},{%8,%9},{%0,%1,%2,%3};"
        : "+f"(c[0]), "+f"(c[1]), "+f"(c[2]), "+f"(c[3])
        : "r"(a0), "r"(a1), "r"(a2), "r"(a3), "r"(b0), "r"(b1));
}
__device__ __forceinline__ void mma16(float* c,
    unsigned a0, unsigned a1, unsigned a2, unsigned a3,
    unsigned b0, unsigned b1)
{
    asm volatile(
        "mma.sync.aligned.m16n8k16.row.col.f32.bf16.bf16.f32 "
        "{%0,%1,%2,%3},{%4,%5,%6,%7},{%8,%9},{%0,%1,%2,%3};"
        : "+f"(c[0]), "+f"(c[1]), "+f"(c[2]), "+f"(c[3])
        : "r"(a0), "r"(a1), "r"(a2), "r"(a3), "r"(b0), "r"(b1));
}

// ---------------- split kernels -------------------------------------------------
__global__ void splitA(const float* __restrict__ src, uint2* __restrict__ dst)
{
    int idx = blockIdx.x * 256 + threadIdx.x;
    float4 v0 = *(const float4*)&src[idx * 8];
    float4 v1 = *(const float4*)&src[idx * 8 + 4];
    dst[idx * 4 + 0] = sbf(v0.x, v0.y);
    dst[idx * 4 + 1] = sbf(v0.z, v0.w);
    dst[idx * 4 + 2] = sbf(v1.x, v1.y);
    dst[idx * 4 + 3] = sbf(v1.z, v1.w);
}

__global__ void splitW4(const float* __restrict__ W0, const float* __restrict__ W1,
                        const float* __restrict__ W2, const float* __restrict__ W3)
{
    int m = blockIdx.x >> 9;
    const float* W = (m == 0) ? W0 : (m == 1) ? W1 : (m == 2) ? W2 : W3;
    uint2* dst = g_ws + m * (MSZ / 2);
    int idx = (blockIdx.x & 511) * 256 + threadIdx.x;
    int kp = idx >> 8;
    int n4 = (idx & 255) * 4;
    float4 r0 = *(const float4*)&W[(2 * kp) * 1024 + n4];
    float4 r1 = *(const float4*)&W[(2 * kp + 1) * 1024 + n4];
    dst[kp * 1024 + n4 + 0] = sbf(r0.x, r1.x);
    dst[kp * 1024 + n4 + 1] = sbf(r0.y, r1.y);
    dst[kp * 1024 + n4 + 2] = sbf(r0.z, r1.z);
    dst[kp * 1024 + n4 + 3] = sbf(r0.w, r1.w);
}

// ---------------- GEMM (3x bf16, double-buffered, 2 blocks/SM) -----------------
#define SA_STR 18
#define SB_STR 68
#define BUF_SZ (128*SA_STR + 16*SB_STR)
#define GEMM_SMEM (2 * BUF_SZ * 8)

__global__ void __launch_bounds__(256, 2) gemm_tc(float* __restrict__ Cout, int mode)
{
    extern __shared__ uint2 sm2[];

    int z = blockIdx.z;
    const uint4* Wm = (const uint4*)(g_ws + (mode == 0 ? z : 3) * (MSZ/2));
    const uint4* Am = (const uint4*)g_xs;

    int tid  = threadIdx.x;
    int lane = tid & 31;
    int wid  = tid >> 5;
    int wm   = wid & 3;
    int wn   = wid >> 2;
    int g    = lane >> 2;
    int tg   = lane & 3;
    int row0 = blockIdx.y * 128;
    int col0 = blockIdx.x * 64;

    int aRow[4], aK4[4], sAi[4];
    #pragma unroll
    for (int e = 0; e < 4; e++) {
        int idx = tid + e * 256;
        aRow[e] = idx >> 3; aK4[e] = idx & 7;
        sAi[e]  = aRow[e] * SA_STR + aK4[e] * 2;
    }
    int bKp = tid >> 4, bC4 = tid & 15;
    int sBi = 128 * SA_STR + bKp * SB_STR + bC4 * 4;
    int bGi = bKp * 512 + col0 / 2 + bC4 * 2;

    float acc[2][4][4];
    #pragma unroll
    for (int mt = 0; mt < 2; mt++)
        #pragma unroll
        for (int nt = 0; nt < 4; nt++)
            #pragma unroll
            for (int e = 0; e < 4; e++) acc[mt][nt][e] = 0.f;

    uint4 av[4], bv0, bv1;
    #pragma unroll
    for (int e = 0; e < 4; e++)
        av[e] = Am[(row0 + aRow[e]) * 256 + aK4[e]];
    bv0 = Wm[bGi];
    bv1 = Wm[bGi + 1];

    {
        uint2* buf = sm2;
        #pragma unroll
        for (int e = 0; e < 4; e++)
            *(uint4*)&buf[sAi[e]] = av[e];
        *(uint4*)&buf[sBi]     = bv0;
        *(uint4*)&buf[sBi + 2] = bv1;
    }
    __syncthreads();

    for (int t = 0; t < 32; t++) {
        uint2* cur = sm2 + (t & 1) * BUF_SZ;
        uint2* nxt = sm2 + ((t & 1) ^ 1) * BUF_SZ;

        if (t < 31) {
            #pragma unroll
            for (int e = 0; e < 4; e++)
                av[e] = Am[(row0 + aRow[e]) * 256 + (t + 1) * 8 + aK4[e]];
            bv0 = Wm[(t + 1) * 16 * 512 + bGi];
            bv1 = Wm[(t + 1) * 16 * 512 + bGi + 1];
        }

        #pragma unroll
        for (int ks = 0; ks < 2; ks++) {
            uint2 Afr[2][4];
            #pragma unroll
            for (int mt = 0; mt < 2; mt++) {
                int rb = (wm * 32 + mt * 16 + g) * SA_STR + ks * 8 + tg;
                Afr[mt][0] = cur[rb];
                Afr[mt][2] = cur[rb + 4];
                Afr[mt][1] = cur[rb + 8 * SA_STR];
                Afr[mt][3] = cur[rb + 8 * SA_STR + 4];
            }
            #pragma unroll
            for (int nt = 0; nt < 4; nt++) {
                int cb = 128 * SA_STR + (ks * 8 + tg) * SB_STR + wn * 32 + nt * 8 + g;
                uint2 B0 = cur[cb];
                uint2 B1 = cur[cb + 4 * SB_STR];
                #pragma unroll
                for (int mt = 0; mt < 2; mt++) {
                    float* c = acc[mt][nt];
                    mma16(c, Afr[mt][0].x, Afr[mt][1].x, Afr[mt][2].x, Afr[mt][3].x,
                          B0.x, B1.x);
                    mma16(c, Afr[mt][0].x, Afr[mt][1].x, Afr[mt][2].x, Afr[mt][3].x,
                          B0.y, B1.y);
                    mma16(c, Afr[mt][0].y, Afr[mt][1].y, Afr[mt][2].y, Afr[mt][3].y,
                          B0.x, B1.x);
                }
            }
        }

        if (t < 31) {
            #pragma unroll
            for (int e = 0; e < 4; e++)
                *(uint4*)&nxt[sAi[e]] = av[e];
            *(uint4*)&nxt[sBi]     = bv0;
            *(uint4*)&nxt[sBi + 2] = bv1;
        }
        __syncthreads();
    }

    if (mode == 1) {
        #pragma unroll
        for (int mt = 0; mt < 2; mt++) {
            int row = row0 + wm * 32 + mt * 16 + g;
            #pragma unroll
            for (int nt = 0; nt < 4; nt++) {
                int col = col0 + wn * 32 + nt * 8 + 2 * tg;
                *(float2*)&Cout[row * 1024 + col] =
                    make_float2(acc[mt][nt][0], acc[mt][nt][1]);
                *(float2*)&Cout[(row + 8) * 1024 + col] =
                    make_float2(acc[mt][nt][2], acc[mt][nt][3]);
            }
        }
    } else {
        float* dst = (z == 0) ? g_q : (z == 1) ? g_k : g_v;
        int h = blockIdx.x;
        #pragma unroll
        for (int mt = 0; mt < 2; mt++) {
            int row = row0 + wm * 32 + mt * 16 + g;
            int b0r = row >> 9, t0r = row & 511;
            int b1r = (row + 8) >> 9, t1r = (row + 8) & 511;
            #pragma unroll
            for (int nt = 0; nt < 4; nt++) {
                int col = wn * 32 + nt * 8 + 2 * tg;
                *(float2*)&dst[(((b0r << 4) + h) * 512 + t0r) * 64 + col] =
                    make_float2(acc[mt][nt][0], acc[mt][nt][1]);
                *(float2*)&dst[(((b1r << 4) + h) * 512 + t1r) * 64 + col] =
                    make_float2(acc[mt][nt][2], acc[mt][nt][3]);
            }
        }
    }
}

// ---------------- RoPE (in place on g_q, g_k) -------------------------------
__global__ void rope_kernel()
{
    int idx = blockIdx.x * blockDim.x + threadIdx.x;
    if (idx >= BHT * 32) return;
    int tok = idx >> 5;
    int j   = idx & 31;
    int t   = tok & 511;
    float inv = expf(-((float)(2 * j) / 64.0f) * 9.210340371976184f);
    float fr  = (float)t * inv;
    float s, c;
    sincosf(fr, &s, &c);

    float* q = g_q + tok * 64;
    float x1 = q[j], x2 = q[j + 32];
    q[j]      = x1 * c - x2 * s;
    q[j + 32] = x1 * s + x2 * c;

    float* k = g_k + tok * 64;
    x1 = k[j]; x2 = k[j + 32];
    k[j]      = x1 * c - x2 * s;
    k[j + 32] = x1 * s + x2 * c;
}

// ---------------- metric (R4): km, k2, U, m = qm+w, c = q2+|Uq|^2 ------------
__global__ void __launch_bounds__(256) metric_kernel(
    const float* __restrict__ Wqm, const float* __restrict__ Wkm,
    const float* __restrict__ Wmetric)
{
    __shared__ float sWqm[64 * 32];
    __shared__ float sWkm[64 * 32];
    __shared__ float sWm [32 * 128];
    int tid = threadIdx.x;
    for (int i = tid; i < 64 * 32; i += 256) { sWqm[i] = Wqm[i]; sWkm[i] = Wkm[i]; }
    for (int i = tid; i < 32 * 128; i += 256) { sWm[i] = Wmetric[i]; }
    __syncthreads();

    const unsigned FULL = 0xffffffffu;
    int w = tid >> 5, lane = tid & 31;
    int tok = blockIdx.x * 8 + w;

    const float* q = g_q + tok * 64;
    const float* k = g_k + tok * 64;
    float a0 = q[lane], a1 = q[lane + 32];
    float b0 = k[lane], b1 = k[lane + 32];

    float accq = 0.f, acck = 0.f;
    #pragma unroll
    for (int d = 0; d < 32; d++) {
        float qd = __shfl_sync(FULL, a0, d);
        float kd = __shfl_sync(FULL, b0, d);
        accq += qd * sWqm[d * 32 + lane];
        acck += kd * sWkm[d * 32 + lane];
    }
    #pragma unroll
    for (int d = 0; d < 32; d++) {
        float qd = __shfl_sync(FULL, a1, d);
        float kd = __shfl_sync(FULL, b1, d);
        accq += qd * sWqm[(d + 32) * 32 + lane];
        acck += kd * sWkm[(d + 32) * 32 + lane];
    }
    float qmv = 1.f / (1.f + expf(-accq));
    float kmv = 1.f / (1.f + expf(-acck));
    g_km[tok * 32 + lane] = kmv;

    float q2 = qmv * qmv, k2 = kmv * kmv;
    #pragma unroll
    for (int o = 16; o > 0; o >>= 1) {
        q2 += __shfl_xor_sync(FULL, q2, o);
        k2 += __shfl_xor_sync(FULL, k2, o);
    }
    if (lane == 0) g_k2[tok] = k2;

    float u0 = 0.f, u1 = 0.f, u2 = 0.f, u3 = 0.f;
    #pragma unroll
    for (int d = 0; d < 32; d++) {
        float qd = __shfl_sync(FULL, qmv, d);
        float4 wv = *(const float4*)&sWm[d * 128 + lane * 4];
        u0 += qd * wv.x; u1 += qd * wv.y; u2 += qd * wv.z; u3 += qd * wv.w;
    }
    *(float4*)&g_U[tok * 128 + lane * 4] = make_float4(u0, u1, u2, u3);

    float p0 = u0 * qmv, p1 = u1 * qmv, p2 = u2 * qmv, p3 = u3 * qmv;
    #pragma unroll
    for (int o = 16; o > 0; o >>= 1) {
        p0 += __shfl_xor_sync(FULL, p0, o);
        p1 += __shfl_xor_sync(FULL, p1, o);
        p2 += __shfl_xor_sync(FULL, p2, o);
        p3 += __shfl_xor_sync(FULL, p3, o);
    }
    float wd = p0 * u0 + p1 * u1 + p2 * u2 + p3 * u3;
    g_m[tok * 32 + lane] = qmv + wd;
    if (lane == 0)
        g_c[tok] = q2 + p0 * p0 + p1 * p1 + p2 * p2 + p3 * p3;
}

// ---------------- attention: tf32 scores (frozen) + bf16-pair PV ---------------
// sKm [d=32][j=64] tf32 split; sV [jp=32][c=64] bf16 j-pair split (transposed);
// sP [i=128][jp=32] bf16 j-pair split.
#define KM_STR 66
#define V_STR  66
#define P_STR  34
#define ATTN_SMEM ((32*KM_STR + 32*V_STR + 128*P_STR) * 8 + 64 * 4)

__global__ void __launch_bounds__(256) attn_mma(const float* __restrict__ temp_ptr)
{
    extern __shared__ uint2 smem[];
    uint2* sKm = smem;                         // [32][KM_STR]
    uint2* sV  = sKm + 32 * KM_STR;            // [32][V_STR]  (jp rows)
    uint2* sP  = sV + 32 * V_STR;              // [128][P_STR] (jp cols)
    float* sK2 = (float*)(sP + 128 * P_STR);   // [64]

    int qt = 3 - (int)(blockIdx.x >> 1);
    int jc = blockIdx.x & 1;
    int bh = blockIdx.y;
    int tok0 = bh * 512 + qt * 128;

    int tid  = threadIdx.x;
    int lane = tid & 31;
    int wid  = tid >> 5;
    int g    = lane >> 2;
    int tg   = lane & 3;
    int r0w  = wid * 16;

    float invT = 1.0f / fmaxf(temp_ptr[0], 0.5f);

    int rA = tok0 + r0w + g;
    int rB = rA + 8;
    int iRelA = qt * 128 + r0w + g;
    int iRelB = iRelA + 8;

    uint2 mm[4][4];
    unsigned uf[4][4][4];
    #pragma unroll
    for (int kk = 0; kk < 4; kk++) {
        int d0 = kk * 8 + tg;
        mm[kk][0] = spl(g_m[rA * 32 + d0]);
        mm[kk][1] = spl(g_m[rB * 32 + d0]);
        mm[kk][2] = spl(g_m[rA * 32 + d0 + 4]);
        mm[kk][3] = spl(g_m[rB * 32 + d0 + 4]);
        float4 uA0 = *(const float4*)&g_U[rA * 128 + d0 * 4];
        float4 uB0 = *(const float4*)&g_U[rB * 128 + d0 * 4];
        float4 uA4 = *(const float4*)&g_U[rA * 128 + (d0 + 4) * 4];
        float4 uB4 = *(const float4*)&g_U[rB * 128 + (d0 + 4) * 4];
        #pragma unroll
        for (int r = 0; r < 4; r++) {
            uf[r][kk][0] = tf32of(((const float*)&uA0)[r]);
            uf[r][kk][1] = tf32of(((const float*)&uB0)[r]);
            uf[r][kk][2] = tf32of(((const float*)&uA4)[r]);
            uf[r][kk][3] = tf32of(((const float*)&uB4)[r]);
        }
    }
    float ci0 = g_c[rA], ci1 = g_c[rB];

    float cpv[8][4];
    #pragma unroll
    for (int nt = 0; nt < 8; nt++)
        #pragma unroll
        for (int e = 0; e < 4; e++) cpv[nt][e] = 0.f;
    float runs0 = 0.f, runs1 = 0.f;

    int sj   = tid >> 2;                       // km staging: 0..63
    int sgrp = tid & 3;

    for (int jt = jc; jt <= 2 * qt + 1; jt += 2) {
        int j0 = jt * 64;
        int tokJ = bh * 512 + j0;
        __syncthreads();
        // ---- stage km (tf32 split, transposed) ----
        {
            float4 k0 = *(const float4*)&g_km[(tokJ + sj) * 32 + sgrp * 8];
            float4 k1 = *(const float4*)&g_km[(tokJ + sj) * 32 + sgrp * 8 + 4];
            #pragma unroll
            for (int t = 0; t < 4; t++)
                sKm[(sgrp * 8 + t) * KM_STR + sj] = spl(((const float*)&k0)[t]);
            #pragma unroll
            for (int t = 0; t < 4; t++)
                sKm[(sgrp * 8 + 4 + t) * KM_STR + sj] = spl(((const float*)&k1)[t]);
            if (tid < 64) sK2[tid] = g_k2[tokJ + tid];
        }
        // ---- stage V (bf16 j-pair split, transposed): 512 tasks ----
        #pragma unroll
        for (int e = 0; e < 2; e++) {
            int idx = tid + e * 256;
            int jp = idx >> 4, c4 = idx & 15;
            float4 v0 = *(const float4*)&g_v[(tokJ + 2 * jp) * 64 + c4 * 4];
            float4 v1 = *(const float4*)&g_v[(tokJ + 2 * jp + 1) * 64 + c4 * 4];
            uint2* d = &sV[jp * V_STR + c4 * 4];
            d[0] = sbf(v0.x, v1.x);
            d[1] = sbf(v0.y, v1.y);
            d[2] = sbf(v0.z, v1.z);
            d[3] = sbf(v0.w, v1.w);
        }
        __syncthreads();

        // ---- scores (tf32 path, frozen) ----
        #pragma unroll
        for (int nt = 0; nt < 8; nt++) {
            float cqk[4] = {0.f, 0.f, 0.f, 0.f};
            float cu0[4] = {0.f, 0.f, 0.f, 0.f};
            float cu1[4] = {0.f, 0.f, 0.f, 0.f};
            float cu2[4] = {0.f, 0.f, 0.f, 0.f};
            float cu3[4] = {0.f, 0.f, 0.f, 0.f};
            #pragma unroll
            for (int kk = 0; kk < 4; kk++) {
                uint2 b0 = sKm[(kk * 8 + tg) * KM_STR + nt * 8 + g];
                uint2 b1 = sKm[(kk * 8 + tg + 4) * KM_STR + nt * 8 + g];
                mma8(cqk, mm[kk][0].x, mm[kk][1].x, mm[kk][2].x, mm[kk][3].x, b0.x, b1.x);
                mma8(cqk, mm[kk][0].x, mm[kk][1].x, mm[kk][2].x, mm[kk][3].x, b0.y, b1.y);
                mma8(cqk, mm[kk][0].y, mm[kk][1].y, mm[kk][2].y, mm[kk][3].y, b0.x, b1.x);
                mma8(cu0, uf[0][kk][0], uf[0][kk][1], uf[0][kk][2], uf[0][kk][3], b0.x, b1.x);
                mma8(cu1, uf[1][kk][0], uf[1][kk][1], uf[1][kk][2], uf[1][kk][3], b0.x, b1.x);
                mma8(cu2, uf[2][kk][0], uf[2][kk][1], uf[2][kk][2], uf[2][kk][3], b0.x, b1.x);
                mma8(cu3, uf[3][kk][0], uf[3][kk][1], uf[3][kk][2], uf[3][kk][3], b0.x, b1.x);
            }
            int colA = nt * 8 + 2 * tg;
            float2 k2p = *(const float2*)&sK2[colA];
            int jRelA = j0 + colA, jRelB = jRelA + 1;
            float p[4];
            #pragma unroll
            for (int e = 0; e < 4; e++) {
                float cival = (e < 2) ? ci0 : ci1;
                float k2v   = (e & 1) ? k2p.y : k2p.x;
                float dist = cival + k2v - 2.f * cqk[e]
                           + cu0[e] * cu0[e] + cu1[e] * cu1[e]
                           + cu2[e] * cu2[e] + cu3[e] * cu3[e];
                p[e] = __expf(-fmaxf(dist, 0.f) * invT);
            }
            if (jRelA > iRelA) p[0] = 0.f;
            if (jRelB > iRelA) p[1] = 0.f;
            if (jRelA > iRelB) p[2] = 0.f;
            if (jRelB > iRelB) p[3] = 0.f;
            runs0 += p[0] + p[1];
            runs1 += p[2] + p[3];
            int jpA = nt * 4 + tg;                      // colA / 2
            sP[(r0w + g) * P_STR + jpA]     = sbf(p[0], p[1]);
            sP[(r0w + g + 8) * P_STR + jpA] = sbf(p[2], p[3]);
        }
        __syncwarp();

        // ---- PV: cpv += P @ V (bf16 3-pass, m16n8k16) ----
        #pragma unroll
        for (int kk = 0; kk < 4; kk++) {
            uint2 A0 = sP[(r0w + g) * P_STR + kk * 8 + tg];
            uint2 A1 = sP[(r0w + g + 8) * P_STR + kk * 8 + tg];
            uint2 A2 = sP[(r0w + g) * P_STR + kk * 8 + tg + 4];
            uint2 A3 = sP[(r0w + g + 8) * P_STR + kk * 8 + tg + 4];
            #pragma unroll
            for (int nt = 0; nt < 8; nt++) {
                uint2 b0 = sV[(kk * 8 + tg) * V_STR + nt * 8 + g];
                uint2 b1 = sV[(kk * 8 + tg + 4) * V_STR + nt * 8 + g];
                mma16(cpv[nt], A0.x, A1.x, A2.x, A3.x, b0.x, b1.x);   // hi*hi
                mma16(cpv[nt], A0.x, A1.x, A2.x, A3.x, b0.y, b1.y);   // hi*lo
                mma16(cpv[nt], A0.y, A1.y, A2.y, A3.y, b0.x, b1.x);   // lo*hi
            }
        }
    }

    const unsigned FULL = 0xffffffffu;
    float s0 = runs0, s1 = runs1;
    s0 += __shfl_xor_sync(FULL, s0, 1); s0 += __shfl_xor_sync(FULL, s0, 2);
    s1 += __shfl_xor_sync(FULL, s1, 1); s1 += __shfl_xor_sync(FULL, s1, 2);
    if (tg == 0) {
        g_psum[jc][rA] = s0;
        g_psum[jc][rB] = s1;
    }
    #pragma unroll
    for (int nt = 0; nt < 8; nt++) {
        int col = nt * 8 + 2 * tg;
        *(float2*)&g_pacc[jc][(size_t)rA * 64 + col] = make_float2(cpv[nt][0], cpv[nt][1]);
        *(float2*)&g_pacc[jc][(size_t)rB * 64 + col] = make_float2(cpv[nt][2], cpv[nt][3]);
    }
}

// ---------------- merge partials -> g_ao -------------------------------------
__global__ void merge_kernel()
{
    int idx = blockIdx.x * 256 + threadIdx.x;
    int tok = idx >> 4, c4 = idx & 15;
    int i = tok & 511;
    float4 a = *(const float4*)&g_pacc[0][tok * 64 + c4 * 4];
    float s = g_psum[0][tok];
    int iq = i & 127;
    if (iq >= 64 || i >= 128) {
        float4 b = *(const float4*)&g_pacc[1][tok * 64 + c4 * 4];
        a.x += b.x; a.y += b.y; a.z += b.z; a.w += b.w;
        s += g_psum[1][tok];
    }
    float inv = 1.f / s;
    int bh = tok >> 9;
    int b = bh >> 4, h = bh & 15;
    float4 o = make_float4(a.x * inv, a.y * inv, a.z * inv, a.w * inv);
    *(float4*)&g_ao[(b * 512 + i) * 1024 + h * 64 + c4 * 4] = o;
}

// ---------------- launch ------------------------------------------------------
extern "C" void kernel_launch(void* const* d_in, const int* in_sizes, int n_in,
                              void* d_out, int out_size)
{
    const float* x    = (const float*)d_in[0];
    const float* Wq   = (const float*)d_in[1];
    const float* Wk   = (const float*)d_in[2];
    const float* Wv   = (const float*)d_in[3];
    const float* Wo   = (const float*)d_in[4];
    const float* Wqm  = (const float*)d_in[5];
    const float* Wkm  = (const float*)d_in[6];
    const float* Wmet = (const float*)d_in[7];
    const float* temp = (const float*)d_in[8];
    float*       out  = (float*)d_out;

    cudaFuncSetAttribute(gemm_tc,
                         cudaFuncAttributeMaxDynamicSharedMemorySize, GEMM_SMEM);
    cudaFuncSetAttribute(attn_mma,
                         cudaFuncAttributeMaxDynamicSharedMemorySize, ATTN_SMEM);

    uint2 *xs;
    cudaGetSymbolAddress((void**)&xs, g_xs);

    splitA<<<512, 256>>>(x, xs);
    splitW4<<<2048, 256>>>(Wq, Wk, Wv, Wo);

    gemm_tc<<<dim3(16, 8, 3), 256, GEMM_SMEM>>>(nullptr, 0);
    rope_kernel<<<(BHT * 32) / 256, 256>>>();
    metric_kernel<<<BHT / 8, 256>>>(Wqm, Wkm, Wmet);
    attn_mma<<<dim3(8, Bb * Hh), 256, ATTN_SMEM>>>(temp);
    merge_kernel<<<1024, 256>>>();

    float* ao;
    cudaGetSymbolAddress((void**)&ao, g_ao);
    splitA<<<512, 256>>>(ao, xs);
    gemm_tc<<<dim3(16, 8, 1), 256, GEMM_SMEM>>>(out, 1);
}

// round 14
// speedup vs baseline: 1.4018x; 1.0343x over previous
#include <cuda_runtime.h>
#include <math.h>

#define Bb   2
#define Tt   512
#define Hh   16
#define BHT  16384
#define MSZ  (1024*1024)

// ---------------- scratch ----------------------------------------------------
__device__ float g_q [BHT*64];
__device__ float g_k [BHT*64];
__device__ float g_v [BHT*64];
__device__ float g_km[BHT*32];
__device__ float g_k2[BHT];
__device__ float g_U [BHT*128];
__device__ float g_m [BHT*32];
__device__ float g_c [BHT];
__device__ float g_pacc[2][BHT*64];
__device__ float g_psum[2][BHT];
// bf16 split-packed operands: uint2 = (ah_pair, al_pair) per 2 k-elements
__device__ uint2 g_xs[MSZ/2];        // A  [1024 rows][512 kp]  (x, then attn out)
__device__ uint2 g_ws[4*(MSZ/2)];    // W  [512 kp][1024 n] x4

// ---------------- bf16 split helpers -------------------------------------------
__device__ __forceinline__ uint2 sbf(float a, float b) {
    unsigned ph;
    asm("cvt.rn.bf16x2.f32 %0,%1,%2;" : "=r"(ph) : "f"(b), "f"(a));
    float ra = a - __uint_as_float(ph << 16);
    float rb = b - __uint_as_float(ph & 0xffff0000u);
    unsigned pl;
    asm("cvt.rn.bf16x2.f32 %0,%1,%2;" : "=r"(pl) : "f"(rb), "f"(ra));
    return make_uint2(ph, pl);
}

// ---------------- tf32 helpers (attention scores) -------------------------------
__device__ __forceinline__ unsigned tf32of(float x) {
    unsigned r; asm("cvt.rna.tf32.f32 %0,%1;" : "=r"(r) : "f"(x)); return r;
}
__device__ __forceinline__ uint2 spl(float x) {
    unsigned h = tf32of(x);
    unsigned l = tf32of(x - __uint_as_float(h));
    return make_uint2(h, l);
}
__device__ __forceinline__ void mma8(float* c,
    unsigned a0, unsigned a1, unsigned a2, unsigned a3,
    unsigned b0, unsigned b1)
{
    asm volatile(
        "mma.sync.aligned.m16n8k8.row.col.f32.tf32.tf32.f32 "
        "{%0,%1,%2,%3},{%4,%5,%6,%7},{%8,%9},{%0,%1,%2,%3};"
        : "+f"(c[0]), "+f"(c[1]), "+f"(c[2]), "+f"(c[3])
        : "r"(a0), "r"(a1), "r"(a2), "r"(a3), "r"(b0), "r"(b1));
}
__device__ __forceinline__ void mma16(float* c,
    unsigned a0, unsigned a1, unsigned a2, unsigned a3,
    unsigned b0, unsigned b1)
{
    asm volatile(
        "mma.sync.aligned.m16n8k16.row.col.f32.bf16.bf16.f32 "
        "{%0,%1,%2,%3},{%4,%5,%6,%7},{%8,%9},{%0,%1,%2,%3};"
        : "+f"(c[0]), "+f"(c[1]), "+f"(c[2]), "+f"(c[3])
        : "r"(a0), "r"(a1), "r"(a2), "r"(a3), "r"(b0), "r"(b1));
}

// ---------------- split kernels -------------------------------------------------
__global__ void splitA(const float* __restrict__ src, uint2* __restrict__ dst)
{
    int idx = blockIdx.x * 256 + threadIdx.x;
    float4 v0 = *(const float4*)&src[idx * 8];
    float4 v1 = *(const float4*)&src[idx * 8 + 4];
    dst[idx * 4 + 0] = sbf(v0.x, v0.y);
    dst[idx * 4 + 1] = sbf(v0.z, v0.w);
    dst[idx * 4 + 2] = sbf(v1.x, v1.y);
    dst[idx * 4 + 3] = sbf(v1.z, v1.w);
}

__global__ void splitW4(const float* __restrict__ W0, const float* __restrict__ W1,
                        const float* __restrict__ W2, const float* __restrict__ W3)
{
    int m = blockIdx.x >> 9;
    const float* W = (m == 0) ? W0 : (m == 1) ? W1 : (m == 2) ? W2 : W3;
    uint2* dst = g_ws + m * (MSZ / 2);
    int idx = (blockIdx.x & 511) * 256 + threadIdx.x;
    int kp = idx >> 8;
    int n4 = (idx & 255) * 4;
    float4 r0 = *(const float4*)&W[(2 * kp) * 1024 + n4];
    float4 r1 = *(const float4*)&W[(2 * kp + 1) * 1024 + n4];
    dst[kp * 1024 + n4 + 0] = sbf(r0.x, r1.x);
    dst[kp * 1024 + n4 + 1] = sbf(r0.y, r1.y);
    dst[kp * 1024 + n4 + 2] = sbf(r0.z, r1.z);
    dst[kp * 1024 + n4 + 3] = sbf(r0.w, r1.w);
}

// ---------------- GEMM (3x bf16, double-buffered, 2 blocks/SM) -----------------
#define SA_STR 18
#define SB_STR 68
#define BUF_SZ (128*SA_STR + 16*SB_STR)
#define GEMM_SMEM (2 * BUF_SZ * 8)

__global__ void __launch_bounds__(256, 2) gemm_tc(float* __restrict__ Cout, int mode)
{
    extern __shared__ uint2 sm2[];

    int z = blockIdx.z;
    const uint4* Wm = (const uint4*)(g_ws + (mode == 0 ? z : 3) * (MSZ/2));
    const uint4* Am = (const uint4*)g_xs;

    int tid  = threadIdx.x;
    int lane = tid & 31;
    int wid  = tid >> 5;
    int wm   = wid & 3;
    int wn   = wid >> 2;
    int g    = lane >> 2;
    int tg   = lane & 3;
    int row0 = blockIdx.y * 128;
    int col0 = blockIdx.x * 64;

    int aRow[4], aK4[4], sAi[4];
    #pragma unroll
    for (int e = 0; e < 4; e++) {
        int idx = tid + e * 256;
        aRow[e] = idx >> 3; aK4[e] = idx & 7;
        sAi[e]  = aRow[e] * SA_STR + aK4[e] * 2;
    }
    int bKp = tid >> 4, bC4 = tid & 15;
    int sBi = 128 * SA_STR + bKp * SB_STR + bC4 * 4;
    int bGi = bKp * 512 + col0 / 2 + bC4 * 2;

    float acc[2][4][4];
    #pragma unroll
    for (int mt = 0; mt < 2; mt++)
        #pragma unroll
        for (int nt = 0; nt < 4; nt++)
            #pragma unroll
            for (int e = 0; e < 4; e++) acc[mt][nt][e] = 0.f;

    uint4 av[4], bv0, bv1;
    #pragma unroll
    for (int e = 0; e < 4; e++)
        av[e] = Am[(row0 + aRow[e]) * 256 + aK4[e]];
    bv0 = Wm[bGi];
    bv1 = Wm[bGi + 1];

    {
        uint2* buf = sm2;
        #pragma unroll
        for (int e = 0; e < 4; e++)
            *(uint4*)&buf[sAi[e]] = av[e];
        *(uint4*)&buf[sBi]     = bv0;
        *(uint4*)&buf[sBi + 2] = bv1;
    }
    __syncthreads();

    for (int t = 0; t < 32; t++) {
        uint2* cur = sm2 + (t & 1) * BUF_SZ;
        uint2* nxt = sm2 + ((t & 1) ^ 1) * BUF_SZ;

        if (t < 31) {
            #pragma unroll
            for (int e = 0; e < 4; e++)
                av[e] = Am[(row0 + aRow[e]) * 256 + (t + 1) * 8 + aK4[e]];
            bv0 = Wm[(t + 1) * 16 * 512 + bGi];
            bv1 = Wm[(t + 1) * 16 * 512 + bGi + 1];
        }

        #pragma unroll
        for (int ks = 0; ks < 2; ks++) {
            uint2 Afr[2][4];
            #pragma unroll
            for (int mt = 0; mt < 2; mt++) {
                int rb = (wm * 32 + mt * 16 + g) * SA_STR + ks * 8 + tg;
                Afr[mt][0] = cur[rb];
                Afr[mt][2] = cur[rb + 4];
                Afr[mt][1] = cur[rb + 8 * SA_STR];
                Afr[mt][3] = cur[rb + 8 * SA_STR + 4];
            }
            #pragma unroll
            for (int nt = 0; nt < 4; nt++) {
                int cb = 128 * SA_STR + (ks * 8 + tg) * SB_STR + wn * 32 + nt * 8 + g;
                uint2 B0 = cur[cb];
                uint2 B1 = cur[cb + 4 * SB_STR];
                #pragma unroll
                for (int mt = 0; mt < 2; mt++) {
                    float* c = acc[mt][nt];
                    mma16(c, Afr[mt][0].x, Afr[mt][1].x, Afr[mt][2].x, Afr[mt][3].x,
                          B0.x, B1.x);
                    mma16(c, Afr[mt][0].x, Afr[mt][1].x, Afr[mt][2].x, Afr[mt][3].x,
                          B0.y, B1.y);
                    mma16(c, Afr[mt][0].y, Afr[mt][1].y, Afr[mt][2].y, Afr[mt][3].y,
                          B0.x, B1.x);
                }
            }
        }

        if (t < 31) {
            #pragma unroll
            for (int e = 0; e < 4; e++)
                *(uint4*)&nxt[sAi[e]] = av[e];
            *(uint4*)&nxt[sBi]     = bv0;
            *(uint4*)&nxt[sBi + 2] = bv1;
        }
        __syncthreads();
    }

    if (mode == 1) {
        #pragma unroll
        for (int mt = 0; mt < 2; mt++) {
            int row = row0 + wm * 32 + mt * 16 + g;
            #pragma unroll
            for (int nt = 0; nt < 4; nt++) {
                int col = col0 + wn * 32 + nt * 8 + 2 * tg;
                *(float2*)&Cout[row * 1024 + col] =
                    make_float2(acc[mt][nt][0], acc[mt][nt][1]);
                *(float2*)&Cout[(row + 8) * 1024 + col] =
                    make_float2(acc[mt][nt][2], acc[mt][nt][3]);
            }
        }
    } else {
        float* dst = (z == 0) ? g_q : (z == 1) ? g_k : g_v;
        int h = blockIdx.x;
        #pragma unroll
        for (int mt = 0; mt < 2; mt++) {
            int row = row0 + wm * 32 + mt * 16 + g;
            int b0r = row >> 9, t0r = row & 511;
            int b1r = (row + 8) >> 9, t1r = (row + 8) & 511;
            #pragma unroll
            for (int nt = 0; nt < 4; nt++) {
                int col = wn * 32 + nt * 8 + 2 * tg;
                *(float2*)&dst[(((b0r << 4) + h) * 512 + t0r) * 64 + col] =
                    make_float2(acc[mt][nt][0], acc[mt][nt][1]);
                *(float2*)&dst[(((b1r << 4) + h) * 512 + t1r) * 64 + col] =
                    make_float2(acc[mt][nt][2], acc[mt][nt][3]);
            }
        }
    }
}

// ---------------- metric with fused RoPE ---------------------------------------
// g_q/g_k hold UN-roped projections; rope applied at load (pair = lane, lane+32).
__global__ void __launch_bounds__(256) metric_kernel(
    const float* __restrict__ Wqm, const float* __restrict__ Wkm,
    const float* __restrict__ Wmetric)
{
    __shared__ float sWqm[64 * 32];
    __shared__ float sWkm[64 * 32];
    __shared__ float sWm [32 * 128];
    int tid = threadIdx.x;
    for (int i = tid; i < 64 * 32; i += 256) { sWqm[i] = Wqm[i]; sWkm[i] = Wkm[i]; }
    for (int i = tid; i < 32 * 128; i += 256) { sWm[i] = Wmetric[i]; }
    __syncthreads();

    const unsigned FULL = 0xffffffffu;
    int w = tid >> 5, lane = tid & 31;
    int tok = blockIdx.x * 8 + w;
    int tpos = tok & 511;

    const float* q = g_q + tok * 64;
    const float* k = g_k + tok * 64;
    float a0r = q[lane], a1r = q[lane + 32];
    float b0r = k[lane], b1r = k[lane + 32];

    // fused RoPE
    float invf = expf(-((float)(2 * lane) / 64.0f) * 9.210340371976184f);
    float s, c;
    sincosf((float)tpos * invf, &s, &c);
    float a0 = a0r * c - a1r * s;
    float a1 = a0r * s + a1r * c;
    float b0 = b0r * c - b1r * s;
    float b1 = b0r * s + b1r * c;

    float accq = 0.f, acck = 0.f;
    #pragma unroll
    for (int d = 0; d < 32; d++) {
        float qd = __shfl_sync(FULL, a0, d);
        float kd = __shfl_sync(FULL, b0, d);
        accq += qd * sWqm[d * 32 + lane];
        acck += kd * sWkm[d * 32 + lane];
    }
    #pragma unroll
    for (int d = 0; d < 32; d++) {
        float qd = __shfl_sync(FULL, a1, d);
        float kd = __shfl_sync(FULL, b1, d);
        accq += qd * sWqm[(d + 32) * 32 + lane];
        acck += kd * sWkm[(d + 32) * 32 + lane];
    }
    float qmv = 1.f / (1.f + expf(-accq));
    float kmv = 1.f / (1.f + expf(-acck));
    g_km[tok * 32 + lane] = kmv;

    float q2 = qmv * qmv, k2 = kmv * kmv;
    #pragma unroll
    for (int o = 16; o > 0; o >>= 1) {
        q2 += __shfl_xor_sync(FULL, q2, o);
        k2 += __shfl_xor_sync(FULL, k2, o);
    }
    if (lane == 0) g_k2[tok] = k2;

    float u0 = 0.f, u1 = 0.f, u2 = 0.f, u3 = 0.f;
    #pragma unroll
    for (int d = 0; d < 32; d++) {
        float qd = __shfl_sync(FULL, qmv, d);
        float4 wv = *(const float4*)&sWm[d * 128 + lane * 4];
        u0 += qd * wv.x; u1 += qd * wv.y; u2 += qd * wv.z; u3 += qd * wv.w;
    }
    *(float4*)&g_U[tok * 128 + lane * 4] = make_float4(u0, u1, u2, u3);

    float p0 = u0 * qmv, p1 = u1 * qmv, p2 = u2 * qmv, p3 = u3 * qmv;
    #pragma unroll
    for (int o = 16; o > 0; o >>= 1) {
        p0 += __shfl_xor_sync(FULL, p0, o);
        p1 += __shfl_xor_sync(FULL, p1, o);
        p2 += __shfl_xor_sync(FULL, p2, o);
        p3 += __shfl_xor_sync(FULL, p3, o);
    }
    float wd = p0 * u0 + p1 * u1 + p2 * u2 + p3 * u3;
    g_m[tok * 32 + lane] = qmv + wd;
    if (lane == 0)
        g_c[tok] = q2 + p0 * p0 + p1 * p1 + p2 * p2 + p3 * p3;
}

// ---------------- attention: tf32 scores + bf16-pair PV (R13, frozen) ----------
#define KM_STR 66
#define V_STR  66
#define P_STR  34
#define ATTN_SMEM ((32*KM_STR + 32*V_STR + 128*P_STR) * 8 + 64 * 4)

__global__ void __launch_bounds__(256) attn_mma(const float* __restrict__ temp_ptr)
{
    extern __shared__ uint2 smem[];
    uint2* sKm = smem;                         // [32][KM_STR]
    uint2* sV  = sKm + 32 * KM_STR;            // [32][V_STR]
    uint2* sP  = sV + 32 * V_STR;              // [128][P_STR]
    float* sK2 = (float*)(sP + 128 * P_STR);   // [64]

    int qt = 3 - (int)(blockIdx.x >> 1);
    int jc = blockIdx.x & 1;
    int bh = blockIdx.y;
    int tok0 = bh * 512 + qt * 128;

    int tid  = threadIdx.x;
    int lane = tid & 31;
    int wid  = tid >> 5;
    int g    = lane >> 2;
    int tg   = lane & 3;
    int r0w  = wid * 16;

    float invT = 1.0f / fmaxf(temp_ptr[0], 0.5f);

    int rA = tok0 + r0w + g;
    int rB = rA + 8;
    int iRelA = qt * 128 + r0w + g;
    int iRelB = iRelA + 8;

    uint2 mm[4][4];
    unsigned uf[4][4][4];
    #pragma unroll
    for (int kk = 0; kk < 4; kk++) {
        int d0 = kk * 8 + tg;
        mm[kk][0] = spl(g_m[rA * 32 + d0]);
        mm[kk][1] = spl(g_m[rB * 32 + d0]);
        mm[kk][2] = spl(g_m[rA * 32 + d0 + 4]);
        mm[kk][3] = spl(g_m[rB * 32 + d0 + 4]);
        float4 uA0 = *(const float4*)&g_U[rA * 128 + d0 * 4];
        float4 uB0 = *(const float4*)&g_U[rB * 128 + d0 * 4];
        float4 uA4 = *(const float4*)&g_U[rA * 128 + (d0 + 4) * 4];
        float4 uB4 = *(const float4*)&g_U[rB * 128 + (d0 + 4) * 4];
        #pragma unroll
        for (int r = 0; r < 4; r++) {
            uf[r][kk][0] = tf32of(((const float*)&uA0)[r]);
            uf[r][kk][1] = tf32of(((const float*)&uB0)[r]);
            uf[r][kk][2] = tf32of(((const float*)&uA4)[r]);
            uf[r][kk][3] = tf32of(((const float*)&uB4)[r]);
        }
    }
    float ci0 = g_c[rA], ci1 = g_c[rB];

    float cpv[8][4];
    #pragma unroll
    for (int nt = 0; nt < 8; nt++)
        #pragma unroll
        for (int e = 0; e < 4; e++) cpv[nt][e] = 0.f;
    float runs0 = 0.f, runs1 = 0.f;

    int sj   = tid >> 2;
    int sgrp = tid & 3;

    for (int jt = jc; jt <= 2 * qt + 1; jt += 2) {
        int j0 = jt * 64;
        int tokJ = bh * 512 + j0;
        __syncthreads();
        {
            float4 k0 = *(const float4*)&g_km[(tokJ + sj) * 32 + sgrp * 8];
            float4 k1 = *(const float4*)&g_km[(tokJ + sj) * 32 + sgrp * 8 + 4];
            #pragma unroll
            for (int t = 0; t < 4; t++)
                sKm[(sgrp * 8 + t) * KM_STR + sj] = spl(((const float*)&k0)[t]);
            #pragma unroll
            for (int t = 0; t < 4; t++)
                sKm[(sgrp * 8 + 4 + t) * KM_STR + sj] = spl(((const float*)&k1)[t]);
            if (tid < 64) sK2[tid] = g_k2[tokJ + tid];
        }
        #pragma unroll
        for (int e = 0; e < 2; e++) {
            int idx = tid + e * 256;
            int jp = idx >> 4, c4 = idx & 15;
            float4 v0 = *(const float4*)&g_v[(tokJ + 2 * jp) * 64 + c4 * 4];
            float4 v1 = *(const float4*)&g_v[(tokJ + 2 * jp + 1) * 64 + c4 * 4];
            uint2* d = &sV[jp * V_STR + c4 * 4];
            d[0] = sbf(v0.x, v1.x);
            d[1] = sbf(v0.y, v1.y);
            d[2] = sbf(v0.z, v1.z);
            d[3] = sbf(v0.w, v1.w);
        }
        __syncthreads();

        #pragma unroll
        for (int nt = 0; nt < 8; nt++) {
            float cqk[4] = {0.f, 0.f, 0.f, 0.f};
            float cu0[4] = {0.f, 0.f, 0.f, 0.f};
            float cu1[4] = {0.f, 0.f, 0.f, 0.f};
            float cu2[4] = {0.f, 0.f, 0.f, 0.f};
            float cu3[4] = {0.f, 0.f, 0.f, 0.f};
            #pragma unroll
            for (int kk = 0; kk < 4; kk++) {
                uint2 b0 = sKm[(kk * 8 + tg) * KM_STR + nt * 8 + g];
                uint2 b1 = sKm[(kk * 8 + tg + 4) * KM_STR + nt * 8 + g];
                mma8(cqk, mm[kk][0].x, mm[kk][1].x, mm[kk][2].x, mm[kk][3].x, b0.x, b1.x);
                mma8(cqk, mm[kk][0].x, mm[kk][1].x, mm[kk][2].x, mm[kk][3].x, b0.y, b1.y);
                mma8(cqk, mm[kk][0].y, mm[kk][1].y, mm[kk][2].y, mm[kk][3].y, b0.x, b1.x);
                mma8(cu0, uf[0][kk][0], uf[0][kk][1], uf[0][kk][2], uf[0][kk][3], b0.x, b1.x);
                mma8(cu1, uf[1][kk][0], uf[1][kk][1], uf[1][kk][2], uf[1][kk][3], b0.x, b1.x);
                mma8(cu2, uf[2][kk][0], uf[2][kk][1], uf[2][kk][2], uf[2][kk][3], b0.x, b1.x);
                mma8(cu3, uf[3][kk][0], uf[3][kk][1], uf[3][kk][2], uf[3][kk][3], b0.x, b1.x);
            }
            int colA = nt * 8 + 2 * tg;
            float2 k2p = *(const float2*)&sK2[colA];
            int jRelA = j0 + colA, jRelB = jRelA + 1;
            float p[4];
            #pragma unroll
            for (int e = 0; e < 4; e++) {
                float cival = (e < 2) ? ci0 : ci1;
                float k2v   = (e & 1) ? k2p.y : k2p.x;
                float dist = cival + k2v - 2.f * cqk[e]
                           + cu0[e] * cu0[e] + cu1[e] * cu1[e]
                           + cu2[e] * cu2[e] + cu3[e] * cu3[e];
                p[e] = __expf(-fmaxf(dist, 0.f) * invT);
            }
            if (jRelA > iRelA) p[0] = 0.f;
            if (jRelB > iRelA) p[1] = 0.f;
            if (jRelA > iRelB) p[2] = 0.f;
            if (jRelB > iRelB) p[3] = 0.f;
            runs0 += p[0] + p[1];
            runs1 += p[2] + p[3];
            int jpA = nt * 4 + tg;
            sP[(r0w + g) * P_STR + jpA]     = sbf(p[0], p[1]);
            sP[(r0w + g + 8) * P_STR + jpA] = sbf(p[2], p[3]);
        }
        __syncwarp();

        #pragma unroll
        for (int kk = 0; kk < 4; kk++) {
            uint2 A0 = sP[(r0w + g) * P_STR + kk * 8 + tg];
            uint2 A1 = sP[(r0w + g + 8) * P_STR + kk * 8 + tg];
            uint2 A2 = sP[(r0w + g) * P_STR + kk * 8 + tg + 4];
            uint2 A3 = sP[(r0w + g + 8) * P_STR + kk * 8 + tg + 4];
            #pragma unroll
            for (int nt = 0; nt < 8; nt++) {
                uint2 b0 = sV[(kk * 8 + tg) * V_STR + nt * 8 + g];
                uint2 b1 = sV[(kk * 8 + tg + 4) * V_STR + nt * 8 + g];
                mma16(cpv[nt], A0.x, A1.x, A2.x, A3.x, b0.x, b1.x);
                mma16(cpv[nt], A0.x, A1.x, A2.x, A3.x, b0.y, b1.y);
                mma16(cpv[nt], A0.y, A1.y, A2.y, A3.y, b0.x, b1.x);
            }
        }
    }

    const unsigned FULL = 0xffffffffu;
    float s0 = runs0, s1 = runs1;
    s0 += __shfl_xor_sync(FULL, s0, 1); s0 += __shfl_xor_sync(FULL, s0, 2);
    s1 += __shfl_xor_sync(FULL, s1, 1); s1 += __shfl_xor_sync(FULL, s1, 2);
    if (tg == 0) {
        g_psum[jc][rA] = s0;
        g_psum[jc][rB] = s1;
    }
    #pragma unroll
    for (int nt = 0; nt < 8; nt++) {
        int col = nt * 8 + 2 * tg;
        *(float2*)&g_pacc[jc][(size_t)rA * 64 + col] = make_float2(cpv[nt][0], cpv[nt][1]);
        *(float2*)&g_pacc[jc][(size_t)rB * 64 + col] = make_float2(cpv[nt][2], cpv[nt][3]);
    }
}

// ---------------- merge partials -> g_xs (bf16 split, ready for mode-1 GEMM) ---
__global__ void merge_kernel()
{
    int idx = blockIdx.x * 256 + threadIdx.x;    // 262144 items
    int tok = idx >> 4, c4 = idx & 15;
    int i = tok & 511;
    float4 a = *(const float4*)&g_pacc[0][tok * 64 + c4 * 4];
    float s = g_psum[0][tok];
    int iq = i & 127;
    if (iq >= 64 || i >= 128) {
        float4 b = *(const float4*)&g_pacc[1][tok * 64 + c4 * 4];
        a.x += b.x; a.y += b.y; a.z += b.z; a.w += b.w;
        s += g_psum[1][tok];
    }
    float inv = 1.f / s;
    int bh = tok >> 9;
    int b = bh >> 4, h = bh & 15;
    // write split-packed directly: row = b*512+i, cols h*64 + c4*4 .. +3
    int row = b * 512 + i;
    int kp = (h * 64 + c4 * 4) >> 1;             // 2 pairs
    g_xs[row * 512 + kp]     = sbf(a.x * inv, a.y * inv);
    g_xs[row * 512 + kp + 1] = sbf(a.z * inv, a.w * inv);
}

// ---------------- launch ------------------------------------------------------
extern "C" void kernel_launch(void* const* d_in, const int* in_sizes, int n_in,
                              void* d_out, int out_size)
{
    const float* x    = (const float*)d_in[0];
    const float* Wq   = (const float*)d_in[1];
    const float* Wk   = (const float*)d_in[2];
    const float* Wv   = (const float*)d_in[3];
    const float* Wo   = (const float*)d_in[4];
    const float* Wqm  = (const float*)d_in[5];
    const float* Wkm  = (const float*)d_in[6];
    const float* Wmet = (const float*)d_in[7];
    const float* temp = (const float*)d_in[8];
    float*       out  = (float*)d_out;

    cudaFuncSetAttribute(gemm_tc,
                         cudaFuncAttributeMaxDynamicSharedMemorySize, GEMM_SMEM);
    cudaFuncSetAttribute(attn_mma,
                         cudaFuncAttributeMaxDynamicSharedMemorySize, ATTN_SMEM);

    uint2 *xs;
    cudaGetSymbolAddress((void**)&xs, g_xs);

    splitA<<<512, 256>>>(x, xs);
    splitW4<<<2048, 256>>>(Wq, Wk, Wv, Wo);

    gemm_tc<<<dim3(16, 8, 3), 256, GEMM_SMEM>>>(nullptr, 0);
    metric_kernel<<<BHT / 8, 256>>>(Wqm, Wkm, Wmet);
    attn_mma<<<dim3(8, Bb * Hh), 256, ATTN_SMEM>>>(temp);
    merge_kernel<<<1024, 256>>>();
    gemm_tc<<<dim3(16, 8, 1), 256, GEMM_SMEM>>>(out, 1);
}

// round 15
// speedup vs baseline: 1.4050x; 1.0023x over previous
#include <cuda_runtime.h>
#include <math.h>

#define Bb   2
#define Tt   512
#define Hh   16
#define BHT  16384
#define MSZ  (1024*1024)

// ---------------- scratch ----------------------------------------------------
__device__ float g_q [BHT*64];
__device__ float g_k [BHT*64];
__device__ float g_v [BHT*64];
__device__ float g_km[BHT*32];
__device__ float g_k2[BHT];
__device__ float g_U [BHT*128];
__device__ float g_m [BHT*32];
__device__ float g_c [BHT];
__device__ float g_pacc[2][BHT*64];
__device__ float g_psum[2][BHT];
// bf16 split-packed operands: uint2 = (ah_pair, al_pair) per 2 k-elements
__device__ uint2 g_xs[MSZ/2];        // A  [1024 rows][512 kp]  (x, then attn out)
__device__ uint2 g_ws[4*(MSZ/2)];    // W  [512 kp][1024 n] x4

// ---------------- bf16 split helpers -------------------------------------------
__device__ __forceinline__ uint2 sbf(float a, float b) {
    unsigned ph;
    asm("cvt.rn.bf16x2.f32 %0,%1,%2;" : "=r"(ph) : "f"(b), "f"(a));
    float ra = a - __uint_as_float(ph << 16);
    float rb = b - __uint_as_float(ph & 0xffff0000u);
    unsigned pl;
    asm("cvt.rn.bf16x2.f32 %0,%1,%2;" : "=r"(pl) : "f"(rb), "f"(ra));
    return make_uint2(ph, pl);
}

// ---------------- tf32 helpers (attention scores) -------------------------------
__device__ __forceinline__ unsigned tf32of(float x) {
    unsigned r; asm("cvt.rna.tf32.f32 %0,%1;" : "=r"(r) : "f"(x)); return r;
}
__device__ __forceinline__ uint2 spl(float x) {
    unsigned h = tf32of(x);
    unsigned l = tf32of(x - __uint_as_float(h));
    return make_uint2(h, l);
}
__device__ __forceinline__ void mma8(float* c,
    unsigned a0, unsigned a1, unsigned a2, unsigned a3,
    unsigned b0, unsigned b1)
{
    asm volatile(
        "mma.sync.aligned.m16n8k8.row.col.f32.tf32.tf32.f32 "
        "{%0,%1,%2,%3},{%4,%5,%6,%7},{%8,%9},{%0,%1,%2,%3};"
        : "+f"(c[0]), "+f"(c[1]), "+f"(c[2]), "+f"(c[3])
        : "r"(a0), "r"(a1), "r"(a2), "r"(a3), "r"(b0), "r"(b1));
}
__device__ __forceinline__ void mma16(float* c,
    unsigned a0, unsigned a1, unsigned a2, unsigned a3,
    unsigned b0, unsigned b1)
{
    asm volatile(
        "mma.sync.aligned.m16n8k16.row.col.f32.bf16.bf16.f32 "
        "{%0,%1,%2,%3},{%4,%5,%6,%7},{%8,%9},{%0,%1,%2,%3};"
        : "+f"(c[0]), "+f"(c[1]), "+f"(c[2]), "+f"(c[3])
        : "r"(a0), "r"(a1), "r"(a2), "r"(a3), "r"(b0), "r"(b1));
}

// ---------------- split kernels -------------------------------------------------
__global__ void splitA(const float* __restrict__ src, uint2* __restrict__ dst)
{
    int idx = blockIdx.x * 256 + threadIdx.x;
    float4 v0 = *(const float4*)&src[idx * 8];
    float4 v1 = *(const float4*)&src[idx * 8 + 4];
    dst[idx * 4 + 0] = sbf(v0.x, v0.y);
    dst[idx * 4 + 1] = sbf(v0.z, v0.w);
    dst[idx * 4 + 2] = sbf(v1.x, v1.y);
    dst[idx * 4 + 3] = sbf(v1.z, v1.w);
}

__global__ void splitW4(const float* __restrict__ W0, const float* __restrict__ W1,
                        const float* __restrict__ W2, const float* __restrict__ W3)
{
    int m = blockIdx.x >> 9;
    const float* W = (m == 0) ? W0 : (m == 1) ? W1 : (m == 2) ? W2 : W3;
    uint2* dst = g_ws + m * (MSZ / 2);
    int idx = (blockIdx.x & 511) * 256 + threadIdx.x;
    int kp = idx >> 8;
    int n4 = (idx & 255) * 4;
    float4 r0 = *(const float4*)&W[(2 * kp) * 1024 + n4];
    float4 r1 = *(const float4*)&W[(2 * kp + 1) * 1024 + n4];
    dst[kp * 1024 + n4 + 0] = sbf(r0.x, r1.x);
    dst[kp * 1024 + n4 + 1] = sbf(r0.y, r1.y);
    dst[kp * 1024 + n4 + 2] = sbf(r0.z, r1.z);
    dst[kp * 1024 + n4 + 3] = sbf(r0.w, r1.w);
}

// ---------------- GEMM (3x bf16, double-buffered, 2 blocks/SM) -----------------
#define SA_STR 18
#define SB_STR 68
#define BUF_SZ (128*SA_STR + 16*SB_STR)
#define GEMM_SMEM (2 * BUF_SZ * 8)

__global__ void __launch_bounds__(256, 2) gemm_tc(float* __restrict__ Cout, int mode)
{
    extern __shared__ uint2 sm2[];

    int z = blockIdx.z;
    const uint4* Wm = (const uint4*)(g_ws + (mode == 0 ? z : 3) * (MSZ/2));
    const uint4* Am = (const uint4*)g_xs;

    int tid  = threadIdx.x;
    int lane = tid & 31;
    int wid  = tid >> 5;
    int wm   = wid & 3;
    int wn   = wid >> 2;
    int g    = lane >> 2;
    int tg   = lane & 3;
    int row0 = blockIdx.y * 128;
    int col0 = blockIdx.x * 64;

    int aRow[4], aK4[4], sAi[4];
    #pragma unroll
    for (int e = 0; e < 4; e++) {
        int idx = tid + e * 256;
        aRow[e] = idx >> 3; aK4[e] = idx & 7;
        sAi[e]  = aRow[e] * SA_STR + aK4[e] * 2;
    }
    int bKp = tid >> 4, bC4 = tid & 15;
    int sBi = 128 * SA_STR + bKp * SB_STR + bC4 * 4;
    int bGi = bKp * 512 + col0 / 2 + bC4 * 2;

    float acc[2][4][4];
    #pragma unroll
    for (int mt = 0; mt < 2; mt++)
        #pragma unroll
        for (int nt = 0; nt < 4; nt++)
            #pragma unroll
            for (int e = 0; e < 4; e++) acc[mt][nt][e] = 0.f;

    uint4 av[4], bv0, bv1;
    #pragma unroll
    for (int e = 0; e < 4; e++)
        av[e] = Am[(row0 + aRow[e]) * 256 + aK4[e]];
    bv0 = Wm[bGi];
    bv1 = Wm[bGi + 1];

    {
        uint2* buf = sm2;
        #pragma unroll
        for (int e = 0; e < 4; e++)
            *(uint4*)&buf[sAi[e]] = av[e];
        *(uint4*)&buf[sBi]     = bv0;
        *(uint4*)&buf[sBi + 2] = bv1;
    }
    __syncthreads();

    for (int t = 0; t < 32; t++) {
        uint2* cur = sm2 + (t & 1) * BUF_SZ;
        uint2* nxt = sm2 + ((t & 1) ^ 1) * BUF_SZ;

        if (t < 31) {
            #pragma unroll
            for (int e = 0; e < 4; e++)
                av[e] = Am[(row0 + aRow[e]) * 256 + (t + 1) * 8 + aK4[e]];
            bv0 = Wm[(t + 1) * 16 * 512 + bGi];
            bv1 = Wm[(t + 1) * 16 * 512 + bGi + 1];
        }

        #pragma unroll
        for (int ks = 0; ks < 2; ks++) {
            uint2 Afr[2][4];
            #pragma unroll
            for (int mt = 0; mt < 2; mt++) {
                int rb = (wm * 32 + mt * 16 + g) * SA_STR + ks * 8 + tg;
                Afr[mt][0] = cur[rb];
                Afr[mt][2] = cur[rb + 4];
                Afr[mt][1] = cur[rb + 8 * SA_STR];
                Afr[mt][3] = cur[rb + 8 * SA_STR + 4];
            }
            #pragma unroll
            for (int nt = 0; nt < 4; nt++) {
                int cb = 128 * SA_STR + (ks * 8 + tg) * SB_STR + wn * 32 + nt * 8 + g;
                uint2 B0 = cur[cb];
                uint2 B1 = cur[cb + 4 * SB_STR];
                #pragma unroll
                for (int mt = 0; mt < 2; mt++) {
                    float* c = acc[mt][nt];
                    mma16(c, Afr[mt][0].x, Afr[mt][1].x, Afr[mt][2].x, Afr[mt][3].x,
                          B0.x, B1.x);
                    mma16(c, Afr[mt][0].x, Afr[mt][1].x, Afr[mt][2].x, Afr[mt][3].x,
                          B0.y, B1.y);
                    mma16(c, Afr[mt][0].y, Afr[mt][1].y, Afr[mt][2].y, Afr[mt][3].y,
                          B0.x, B1.x);
                }
            }
        }

        if (t < 31) {
            #pragma unroll
            for (int e = 0; e < 4; e++)
                *(uint4*)&nxt[sAi[e]] = av[e];
            *(uint4*)&nxt[sBi]     = bv0;
            *(uint4*)&nxt[sBi + 2] = bv1;
        }
        __syncthreads();
    }

    if (mode == 1) {
        #pragma unroll
        for (int mt = 0; mt < 2; mt++) {
            int row = row0 + wm * 32 + mt * 16 + g;
            #pragma unroll
            for (int nt = 0; nt < 4; nt++) {
                int col = col0 + wn * 32 + nt * 8 + 2 * tg;
                *(float2*)&Cout[row * 1024 + col] =
                    make_float2(acc[mt][nt][0], acc[mt][nt][1]);
                *(float2*)&Cout[(row + 8) * 1024 + col] =
                    make_float2(acc[mt][nt][2], acc[mt][nt][3]);
            }
        }
    } else {
        float* dst = (z == 0) ? g_q : (z == 1) ? g_k : g_v;
        int h = blockIdx.x;
        #pragma unroll
        for (int mt = 0; mt < 2; mt++) {
            int row = row0 + wm * 32 + mt * 16 + g;
            int b0r = row >> 9, t0r = row & 511;
            int b1r = (row + 8) >> 9, t1r = (row + 8) & 511;
            #pragma unroll
            for (int nt = 0; nt < 4; nt++) {
                int col = wn * 32 + nt * 8 + 2 * tg;
                *(float2*)&dst[(((b0r << 4) + h) * 512 + t0r) * 64 + col] =
                    make_float2(acc[mt][nt][0], acc[mt][nt][1]);
                *(float2*)&dst[(((b1r << 4) + h) * 512 + t1r) * 64 + col] =
                    make_float2(acc[mt][nt][2], acc[mt][nt][3]);
            }
        }
    }
}

// ---------------- metric with fused RoPE, 64 tokens/block ----------------------
__global__ void __launch_bounds__(256) metric_kernel(
    const float* __restrict__ Wqm, const float* __restrict__ Wkm,
    const float* __restrict__ Wmetric)
{
    __shared__ float sWqm[64 * 32];
    __shared__ float sWkm[64 * 32];
    __shared__ float sWm [32 * 128];
    int tid = threadIdx.x;
    for (int i = tid; i < 64 * 32; i += 256) { sWqm[i] = Wqm[i]; sWkm[i] = Wkm[i]; }
    for (int i = tid; i < 32 * 128; i += 256) { sWm[i] = Wmetric[i]; }
    __syncthreads();

    const unsigned FULL = 0xffffffffu;
    int w = tid >> 5, lane = tid & 31;
    float invf = expf(-((float)(2 * lane) / 64.0f) * 9.210340371976184f);

    #pragma unroll 2
    for (int it = 0; it < 8; it++) {
        int tok = blockIdx.x * 64 + it * 8 + w;
        int tpos = tok & 511;

        const float* q = g_q + tok * 64;
        const float* k = g_k + tok * 64;
        float a0r = q[lane], a1r = q[lane + 32];
        float b0r = k[lane], b1r = k[lane + 32];

        // fused RoPE
        float s, c;
        sincosf((float)tpos * invf, &s, &c);
        float a0 = a0r * c - a1r * s;
        float a1 = a0r * s + a1r * c;
        float b0 = b0r * c - b1r * s;
        float b1 = b0r * s + b1r * c;

        float accq = 0.f, acck = 0.f;
        #pragma unroll
        for (int d = 0; d < 32; d++) {
            float qd = __shfl_sync(FULL, a0, d);
            float kd = __shfl_sync(FULL, b0, d);
            accq += qd * sWqm[d * 32 + lane];
            acck += kd * sWkm[d * 32 + lane];
        }
        #pragma unroll
        for (int d = 0; d < 32; d++) {
            float qd = __shfl_sync(FULL, a1, d);
            float kd = __shfl_sync(FULL, b1, d);
            accq += qd * sWqm[(d + 32) * 32 + lane];
            acck += kd * sWkm[(d + 32) * 32 + lane];
        }
        float qmv = 1.f / (1.f + expf(-accq));
        float kmv = 1.f / (1.f + expf(-acck));
        g_km[tok * 32 + lane] = kmv;

        float q2 = qmv * qmv, k2 = kmv * kmv;
        #pragma unroll
        for (int o = 16; o > 0; o >>= 1) {
            q2 += __shfl_xor_sync(FULL, q2, o);
            k2 += __shfl_xor_sync(FULL, k2, o);
        }
        if (lane == 0) g_k2[tok] = k2;

        float u0 = 0.f, u1 = 0.f, u2 = 0.f, u3 = 0.f;
        #pragma unroll
        for (int d = 0; d < 32; d++) {
            float qd = __shfl_sync(FULL, qmv, d);
            float4 wv = *(const float4*)&sWm[d * 128 + lane * 4];
            u0 += qd * wv.x; u1 += qd * wv.y; u2 += qd * wv.z; u3 += qd * wv.w;
        }
        *(float4*)&g_U[tok * 128 + lane * 4] = make_float4(u0, u1, u2, u3);

        float p0 = u0 * qmv, p1 = u1 * qmv, p2 = u2 * qmv, p3 = u3 * qmv;
        #pragma unroll
        for (int o = 16; o > 0; o >>= 1) {
            p0 += __shfl_xor_sync(FULL, p0, o);
            p1 += __shfl_xor_sync(FULL, p1, o);
            p2 += __shfl_xor_sync(FULL, p2, o);
            p3 += __shfl_xor_sync(FULL, p3, o);
        }
        float wd = p0 * u0 + p1 * u1 + p2 * u2 + p3 * u3;
        g_m[tok * 32 + lane] = qmv + wd;
        if (lane == 0)
            g_c[tok] = q2 + p0 * p0 + p1 * p1 + p2 * p2 + p3 * p3;
    }
}

// ---------------- attention: tf32 scores + bf16-pair PV (R13, frozen) ----------
#define KM_STR 66
#define V_STR  66
#define P_STR  34
#define ATTN_SMEM ((32*KM_STR + 32*V_STR + 128*P_STR) * 8 + 64 * 4)

__global__ void __launch_bounds__(256) attn_mma(const float* __restrict__ temp_ptr)
{
    extern __shared__ uint2 smem[];
    uint2* sKm = smem;                         // [32][KM_STR]
    uint2* sV  = sKm + 32 * KM_STR;            // [32][V_STR]
    uint2* sP  = sV + 32 * V_STR;              // [128][P_STR]
    float* sK2 = (float*)(sP + 128 * P_STR);   // [64]

    int qt = 3 - (int)(blockIdx.x >> 1);
    int jc = blockIdx.x & 1;
    int bh = blockIdx.y;
    int tok0 = bh * 512 + qt * 128;

    int tid  = threadIdx.x;
    int lane = tid & 31;
    int wid  = tid >> 5;
    int g    = lane >> 2;
    int tg   = lane & 3;
    int r0w  = wid * 16;

    float invT = 1.0f / fmaxf(temp_ptr[0], 0.5f);

    int rA = tok0 + r0w + g;
    int rB = rA + 8;
    int iRelA = qt * 128 + r0w + g;
    int iRelB = iRelA + 8;

    uint2 mm[4][4];
    unsigned uf[4][4][4];
    #pragma unroll
    for (int kk = 0; kk < 4; kk++) {
        int d0 = kk * 8 + tg;
        mm[kk][0] = spl(g_m[rA * 32 + d0]);
        mm[kk][1] = spl(g_m[rB * 32 + d0]);
        mm[kk][2] = spl(g_m[rA * 32 + d0 + 4]);
        mm[kk][3] = spl(g_m[rB * 32 + d0 + 4]);
        float4 uA0 = *(const float4*)&g_U[rA * 128 + d0 * 4];
        float4 uB0 = *(const float4*)&g_U[rB * 128 + d0 * 4];
        float4 uA4 = *(const float4*)&g_U[rA * 128 + (d0 + 4) * 4];
        float4 uB4 = *(const float4*)&g_U[rB * 128 + (d0 + 4) * 4];
        #pragma unroll
        for (int r = 0; r < 4; r++) {
            uf[r][kk][0] = tf32of(((const float*)&uA0)[r]);
            uf[r][kk][1] = tf32of(((const float*)&uB0)[r]);
            uf[r][kk][2] = tf32of(((const float*)&uA4)[r]);
            uf[r][kk][3] = tf32of(((const float*)&uB4)[r]);
        }
    }
    float ci0 = g_c[rA], ci1 = g_c[rB];

    float cpv[8][4];
    #pragma unroll
    for (int nt = 0; nt < 8; nt++)
        #pragma unroll
        for (int e = 0; e < 4; e++) cpv[nt][e] = 0.f;
    float runs0 = 0.f, runs1 = 0.f;

    int sj   = tid >> 2;
    int sgrp = tid & 3;

    for (int jt = jc; jt <= 2 * qt + 1; jt += 2) {
        int j0 = jt * 64;
        int tokJ = bh * 512 + j0;
        __syncthreads();
        {
            float4 k0 = *(const float4*)&g_km[(tokJ + sj) * 32 + sgrp * 8];
            float4 k1 = *(const float4*)&g_km[(tokJ + sj) * 32 + sgrp * 8 + 4];
            #pragma unroll
            for (int t = 0; t < 4; t++)
                sKm[(sgrp * 8 + t) * KM_STR + sj] = spl(((const float*)&k0)[t]);
            #pragma unroll
            for (int t = 0; t < 4; t++)
                sKm[(sgrp * 8 + 4 + t) * KM_STR + sj] = spl(((const float*)&k1)[t]);
            if (tid < 64) sK2[tid] = g_k2[tokJ + tid];
        }
        #pragma unroll
        for (int e = 0; e < 2; e++) {
            int idx = tid + e * 256;
            int jp = idx >> 4, c4 = idx & 15;
            float4 v0 = *(const float4*)&g_v[(tokJ + 2 * jp) * 64 + c4 * 4];
            float4 v1 = *(const float4*)&g_v[(tokJ + 2 * jp + 1) * 64 + c4 * 4];
            uint2* d = &sV[jp * V_STR + c4 * 4];
            d[0] = sbf(v0.x, v1.x);
            d[1] = sbf(v0.y, v1.y);
            d[2] = sbf(v0.z, v1.z);
            d[3] = sbf(v0.w, v1.w);
        }
        __syncthreads();

        #pragma unroll
        for (int nt = 0; nt < 8; nt++) {
            float cqk[4] = {0.f, 0.f, 0.f, 0.f};
            float cu0[4] = {0.f, 0.f, 0.f, 0.f};
            float cu1[4] = {0.f, 0.f, 0.f, 0.f};
            float cu2[4] = {0.f, 0.f, 0.f, 0.f};
            float cu3[4] = {0.f, 0.f, 0.f, 0.f};
            #pragma unroll
            for (int kk = 0; kk < 4; kk++) {
                uint2 b0 = sKm[(kk * 8 + tg) * KM_STR + nt * 8 + g];
                uint2 b1 = sKm[(kk * 8 + tg + 4) * KM_STR + nt * 8 + g];
                mma8(cqk, mm[kk][0].x, mm[kk][1].x, mm[kk][2].x, mm[kk][3].x, b0.x, b1.x);
                mma8(cqk, mm[kk][0].x, mm[kk][1].x, mm[kk][2].x, mm[kk][3].x, b0.y, b1.y);
                mma8(cqk, mm[kk][0].y, mm[kk][1].y, mm[kk][2].y, mm[kk][3].y, b0.x, b1.x);
                mma8(cu0, uf[0][kk][0], uf[0][kk][1], uf[0][kk][2], uf[0][kk][3], b0.x, b1.x);
                mma8(cu1, uf[1][kk][0], uf[1][kk][1], uf[1][kk][2], uf[1][kk][3], b0.x, b1.x);
                mma8(cu2, uf[2][kk][0], uf[2][kk][1], uf[2][kk][2], uf[2][kk][3], b0.x, b1.x);
                mma8(cu3, uf[3][kk][0], uf[3][kk][1], uf[3][kk][2], uf[3][kk][3], b0.x, b1.x);
            }
            int colA = nt * 8 + 2 * tg;
            float2 k2p = *(const float2*)&sK2[colA];
            int jRelA = j0 + colA, jRelB = jRelA + 1;
            float p[4];
            #pragma unroll
            for (int e = 0; e < 4; e++) {
                float cival = (e < 2) ? ci0 : ci1;
                float k2v   = (e & 1) ? k2p.y : k2p.x;
                float dist = cival + k2v - 2.f * cqk[e]
                           + cu0[e] * cu0[e] + cu1[e] * cu1[e]
                           + cu2[e] * cu2[e] + cu3[e] * cu3[e];
                p[e] = __expf(-fmaxf(dist, 0.f) * invT);
            }
            if (jRelA > iRelA) p[0] = 0.f;
            if (jRelB > iRelA) p[1] = 0.f;
            if (jRelA > iRelB) p[2] = 0.f;
            if (jRelB > iRelB) p[3] = 0.f;
            runs0 += p[0] + p[1];
            runs1 += p[2] + p[3];
            int jpA = nt * 4 + tg;
            sP[(r0w + g) * P_STR + jpA]     = sbf(p[0], p[1]);
            sP[(r0w + g + 8) * P_STR + jpA] = sbf(p[2], p[3]);
        }
        __syncwarp();

        #pragma unroll
        for (int kk = 0; kk < 4; kk++) {
            uint2 A0 = sP[(r0w + g) * P_STR + kk * 8 + tg];
            uint2 A1 = sP[(r0w + g + 8) * P_STR + kk * 8 + tg];
            uint2 A2 = sP[(r0w + g) * P_STR + kk * 8 + tg + 4];
            uint2 A3 = sP[(r0w + g + 8) * P_STR + kk * 8 + tg + 4];
            #pragma unroll
            for (int nt = 0; nt < 8; nt++) {
                uint2 b0 = sV[(kk * 8 + tg) * V_STR + nt * 8 + g];
                uint2 b1 = sV[(kk * 8 + tg + 4) * V_STR + nt * 8 + g];
                mma16(cpv[nt], A0.x, A1.x, A2.x, A3.x, b0.x, b1.x);
                mma16(cpv[nt], A0.x, A1.x, A2.x, A3.x, b0.y, b1.y);
                mma16(cpv[nt], A0.y, A1.y, A2.y, A3.y, b0.x, b1.x);
            }
        }
    }

    const unsigned FULL = 0xffffffffu;
    float s0 = runs0, s1 = runs1;
    s0 += __shfl_xor_sync(FULL, s0, 1); s0 += __shfl_xor_sync(FULL, s0, 2);
    s1 += __shfl_xor_sync(FULL, s1, 1); s1 += __shfl_xor_sync(FULL, s1, 2);
    if (tg == 0) {
        g_psum[jc][rA] = s0;
        g_psum[jc][rB] = s1;
    }
    #pragma unroll
    for (int nt = 0; nt < 8; nt++) {
        int col = nt * 8 + 2 * tg;
        *(float2*)&g_pacc[jc][(size_t)rA * 64 + col] = make_float2(cpv[nt][0], cpv[nt][1]);
        *(float2*)&g_pacc[jc][(size_t)rB * 64 + col] = make_float2(cpv[nt][2], cpv[nt][3]);
    }
}

// ---------------- merge partials -> g_xs (bf16 split, ready for mode-1 GEMM) ---
__global__ void merge_kernel()
{
    int idx = blockIdx.x * 256 + threadIdx.x;    // 262144 items
    int tok = idx >> 4, c4 = idx & 15;
    int i = tok & 511;
    float4 a = *(const float4*)&g_pacc[0][tok * 64 + c4 * 4];
    float s = g_psum[0][tok];
    int iq = i & 127;
    if (iq >= 64 || i >= 128) {
        float4 b = *(const float4*)&g_pacc[1][tok * 64 + c4 * 4];
        a.x += b.x; a.y += b.y; a.z += b.z; a.w += b.w;
        s += g_psum[1][tok];
    }
    float inv = 1.f / s;
    int bh = tok >> 9;
    int b = bh >> 4, h = bh & 15;
    int row = b * 512 + i;
    int kp = (h * 64 + c4 * 4) >> 1;
    g_xs[row * 512 + kp]     = sbf(a.x * inv, a.y * inv);
    g_xs[row * 512 + kp + 1] = sbf(a.z * inv, a.w * inv);
}

// ---------------- launch ------------------------------------------------------
extern "C" void kernel_launch(void* const* d_in, const int* in_sizes, int n_in,
                              void* d_out, int out_size)
{
    const float* x    = (const float*)d_in[0];
    const float* Wq   = (const float*)d_in[1];
    const float* Wk   = (const float*)d_in[2];
    const float* Wv   = (const float*)d_in[3];
    const float* Wo   = (const float*)d_in[4];
    const float* Wqm  = (const float*)d_in[5];
    const float* Wkm  = (const float*)d_in[6];
    const float* Wmet = (const float*)d_in[7];
    const float* temp = (const float*)d_in[8];
    float*       out  = (float*)d_out;

    cudaFuncSetAttribute(gemm_tc,
                         cudaFuncAttributeMaxDynamicSharedMemorySize, GEMM_SMEM);
    cudaFuncSetAttribute(attn_mma,
                         cudaFuncAttributeMaxDynamicSharedMemorySize, ATTN_SMEM);

    uint2 *xs;
    cudaGetSymbolAddress((void**)&xs, g_xs);

    splitA<<<512, 256>>>(x, xs);
    splitW4<<<2048, 256>>>(Wq, Wk, Wv, Wo);

    gemm_tc<<<dim3(16, 8, 3), 256, GEMM_SMEM>>>(nullptr, 0);
    metric_kernel<<<BHT / 64, 256>>>(Wqm, Wkm, Wmet);
    attn_mma<<<dim3(8, Bb * Hh), 256, ATTN_SMEM>>>(temp);
    merge_kernel<<<1024, 256>>>();
    gemm_tc<<<dim3(16, 8, 1), 256, GEMM_SMEM>>>(out, 1);
}

// round 16
// speedup vs baseline: 1.4135x; 1.0060x over previous
#include <cuda_runtime.h>
#include <math.h>

#define Bb   2
#define Tt   512
#define Hh   16
#define BHT  16384
#define MSZ  (1024*1024)

// ---------------- scratch ----------------------------------------------------
__device__ float g_q [BHT*64];
__device__ float g_k [BHT*64];
__device__ float g_v [BHT*64];
__device__ float g_km[BHT*32];
__device__ float g_k2[BHT];
__device__ float g_U [BHT*128];
__device__ float g_m [BHT*32];
__device__ float g_c [BHT];
__device__ float g_pacc[2][BHT*64];
__device__ float g_psum[2][BHT];
// bf16 split-packed operands: uint2 = (ah_pair, al_pair) per 2 k-elements
__device__ uint2 g_xs[MSZ/2];        // A  [1024 rows][512 kp]  (x, then attn out)
__device__ uint2 g_ws[4*(MSZ/2)];    // W  [512 kp][1024 n] x4

// ---------------- bf16 split helpers -------------------------------------------
__device__ __forceinline__ uint2 sbf(float a, float b) {
    unsigned ph;
    asm("cvt.rn.bf16x2.f32 %0,%1,%2;" : "=r"(ph) : "f"(b), "f"(a));
    float ra = a - __uint_as_float(ph << 16);
    float rb = b - __uint_as_float(ph & 0xffff0000u);
    unsigned pl;
    asm("cvt.rn.bf16x2.f32 %0,%1,%2;" : "=r"(pl) : "f"(rb), "f"(ra));
    return make_uint2(ph, pl);
}

// ---------------- tf32 helpers (attention scores) -------------------------------
__device__ __forceinline__ unsigned tf32of(float x) {
    unsigned r; asm("cvt.rna.tf32.f32 %0,%1;" : "=r"(r) : "f"(x)); return r;
}
__device__ __forceinline__ uint2 spl(float x) {
    unsigned h = tf32of(x);
    unsigned l = tf32of(x - __uint_as_float(h));
    return make_uint2(h, l);
}
__device__ __forceinline__ void mma8(float* c,
    unsigned a0, unsigned a1, unsigned a2, unsigned a3,
    unsigned b0, unsigned b1)
{
    asm volatile(
        "mma.sync.aligned.m16n8k8.row.col.f32.tf32.tf32.f32 "
        "{%0,%1,%2,%3},{%4,%5,%6,%7},{%8,%9},{%0,%1,%2,%3};"
        : "+f"(c[0]), "+f"(c[1]), "+f"(c[2]), "+f"(c[3])
        : "r"(a0), "r"(a1), "r"(a2), "r"(a3), "r"(b0), "r"(b1));
}
__device__ __forceinline__ void mma16(float* c,
    unsigned a0, unsigned a1, unsigned a2, unsigned a3,
    unsigned b0, unsigned b1)
{
    asm volatile(
        "mma.sync.aligned.m16n8k16.row.col.f32.bf16.bf16.f32 "
        "{%0,%1,%2,%3},{%4,%5,%6,%7},{%8,%9},{%0,%1,%2,%3};"
        : "+f"(c[0]), "+f"(c[1]), "+f"(c[2]), "+f"(c[3])
        : "r"(a0), "r"(a1), "r"(a2), "r"(a3), "r"(b0), "r"(b1));
}

// ---------------- split kernels -------------------------------------------------
__global__ void splitA(const float* __restrict__ src, uint2* __restrict__ dst)
{
    int idx = blockIdx.x * 256 + threadIdx.x;
    float4 v0 = *(const float4*)&src[idx * 8];
    float4 v1 = *(const float4*)&src[idx * 8 + 4];
    dst[idx * 4 + 0] = sbf(v0.x, v0.y);
    dst[idx * 4 + 1] = sbf(v0.z, v0.w);
    dst[idx * 4 + 2] = sbf(v1.x, v1.y);
    dst[idx * 4 + 3] = sbf(v1.z, v1.w);
}

__global__ void splitW4(const float* __restrict__ W0, const float* __restrict__ W1,
                        const float* __restrict__ W2, const float* __restrict__ W3)
{
    int m = blockIdx.x >> 9;
    const float* W = (m == 0) ? W0 : (m == 1) ? W1 : (m == 2) ? W2 : W3;
    uint2* dst = g_ws + m * (MSZ / 2);
    int idx = (blockIdx.x & 511) * 256 + threadIdx.x;
    int kp = idx >> 8;
    int n4 = (idx & 255) * 4;
    float4 r0 = *(const float4*)&W[(2 * kp) * 1024 + n4];
    float4 r1 = *(const float4*)&W[(2 * kp + 1) * 1024 + n4];
    dst[kp * 1024 + n4 + 0] = sbf(r0.x, r1.x);
    dst[kp * 1024 + n4 + 1] = sbf(r0.y, r1.y);
    dst[kp * 1024 + n4 + 2] = sbf(r0.z, r1.z);
    dst[kp * 1024 + n4 + 3] = sbf(r0.w, r1.w);
}

// ---------------- GEMM (3x bf16, double-buffered, 2 blocks/SM) -----------------
#define SA_STR 18
#define SB_STR 68
#define BUF_SZ (128*SA_STR + 16*SB_STR)
#define GEMM_SMEM (2 * BUF_SZ * 8)

__global__ void __launch_bounds__(256, 2) gemm_tc(float* __restrict__ Cout, int mode)
{
    extern __shared__ uint2 sm2[];

    int z = blockIdx.z;
    const uint4* Wm = (const uint4*)(g_ws + (mode == 0 ? z : 3) * (MSZ/2));
    const uint4* Am = (const uint4*)g_xs;

    int tid  = threadIdx.x;
    int lane = tid & 31;
    int wid  = tid >> 5;
    int wm   = wid & 3;
    int wn   = wid >> 2;
    int g    = lane >> 2;
    int tg   = lane & 3;
    int row0 = blockIdx.y * 128;
    int col0 = blockIdx.x * 64;

    int aRow[4], aK4[4], sAi[4];
    #pragma unroll
    for (int e = 0; e < 4; e++) {
        int idx = tid + e * 256;
        aRow[e] = idx >> 3; aK4[e] = idx & 7;
        sAi[e]  = aRow[e] * SA_STR + aK4[e] * 2;
    }
    int bKp = tid >> 4, bC4 = tid & 15;
    int sBi = 128 * SA_STR + bKp * SB_STR + bC4 * 4;
    int bGi = bKp * 512 + col0 / 2 + bC4 * 2;

    float acc[2][4][4];
    #pragma unroll
    for (int mt = 0; mt < 2; mt++)
        #pragma unroll
        for (int nt = 0; nt < 4; nt++)
            #pragma unroll
            for (int e = 0; e < 4; e++) acc[mt][nt][e] = 0.f;

    uint4 av[4], bv0, bv1;
    #pragma unroll
    for (int e = 0; e < 4; e++)
        av[e] = Am[(row0 + aRow[e]) * 256 + aK4[e]];
    bv0 = Wm[bGi];
    bv1 = Wm[bGi + 1];

    {
        uint2* buf = sm2;
        #pragma unroll
        for (int e = 0; e < 4; e++)
            *(uint4*)&buf[sAi[e]] = av[e];
        *(uint4*)&buf[sBi]     = bv0;
        *(uint4*)&buf[sBi + 2] = bv1;
    }
    __syncthreads();

    for (int t = 0; t < 32; t++) {
        uint2* cur = sm2 + (t & 1) * BUF_SZ;
        uint2* nxt = sm2 + ((t & 1) ^ 1) * BUF_SZ;

        if (t < 31) {
            #pragma unroll
            for (int e = 0; e < 4; e++)
                av[e] = Am[(row0 + aRow[e]) * 256 + (t + 1) * 8 + aK4[e]];
            bv0 = Wm[(t + 1) * 16 * 512 + bGi];
            bv1 = Wm[(t + 1) * 16 * 512 + bGi + 1];
        }

        #pragma unroll
        for (int ks = 0; ks < 2; ks++) {
            uint2 Afr[2][4];
            #pragma unroll
            for (int mt = 0; mt < 2; mt++) {
                int rb = (wm * 32 + mt * 16 + g) * SA_STR + ks * 8 + tg;
                Afr[mt][0] = cur[rb];
                Afr[mt][2] = cur[rb + 4];
                Afr[mt][1] = cur[rb + 8 * SA_STR];
                Afr[mt][3] = cur[rb + 8 * SA_STR + 4];
            }
            #pragma unroll
            for (int nt = 0; nt < 4; nt++) {
                int cb = 128 * SA_STR + (ks * 8 + tg) * SB_STR + wn * 32 + nt * 8 + g;
                uint2 B0 = cur[cb];
                uint2 B1 = cur[cb + 4 * SB_STR];
                #pragma unroll
                for (int mt = 0; mt < 2; mt++) {
                    float* c = acc[mt][nt];
                    mma16(c, Afr[mt][0].x, Afr[mt][1].x, Afr[mt][2].x, Afr[mt][3].x,
                          B0.x, B1.x);
                    mma16(c, Afr[mt][0].x, Afr[mt][1].x, Afr[mt][2].x, Afr[mt][3].x,
                          B0.y, B1.y);
                    mma16(c, Afr[mt][0].y, Afr[mt][1].y, Afr[mt][2].y, Afr[mt][3].y,
                          B0.x, B1.x);
                }
            }
        }

        if (t < 31) {
            #pragma unroll
            for (int e = 0; e < 4; e++)
                *(uint4*)&nxt[sAi[e]] = av[e];
            *(uint4*)&nxt[sBi]     = bv0;
            *(uint4*)&nxt[sBi + 2] = bv1;
        }
        __syncthreads();
    }

    if (mode == 1) {
        #pragma unroll
        for (int mt = 0; mt < 2; mt++) {
            int row = row0 + wm * 32 + mt * 16 + g;
            #pragma unroll
            for (int nt = 0; nt < 4; nt++) {
                int col = col0 + wn * 32 + nt * 8 + 2 * tg;
                *(float2*)&Cout[row * 1024 + col] =
                    make_float2(acc[mt][nt][0], acc[mt][nt][1]);
                *(float2*)&Cout[(row + 8) * 1024 + col] =
                    make_float2(acc[mt][nt][2], acc[mt][nt][3]);
            }
        }
    } else {
        float* dst = (z == 0) ? g_q : (z == 1) ? g_k : g_v;
        int h = blockIdx.x;
        #pragma unroll
        for (int mt = 0; mt < 2; mt++) {
            int row = row0 + wm * 32 + mt * 16 + g;
            int b0r = row >> 9, t0r = row & 511;
            int b1r = (row + 8) >> 9, t1r = (row + 8) & 511;
            #pragma unroll
            for (int nt = 0; nt < 4; nt++) {
                int col = wn * 32 + nt * 8 + 2 * tg;
                *(float2*)&dst[(((b0r << 4) + h) * 512 + t0r) * 64 + col] =
                    make_float2(acc[mt][nt][0], acc[mt][nt][1]);
                *(float2*)&dst[(((b1r << 4) + h) * 512 + t1r) * 64 + col] =
                    make_float2(acc[mt][nt][2], acc[mt][nt][3]);
            }
        }
    }
}

// ---------------- metric with fused RoPE, 64 tokens/block, no outer unroll -----
__global__ void __launch_bounds__(256) metric_kernel(
    const float* __restrict__ Wqm, const float* __restrict__ Wkm,
    const float* __restrict__ Wmetric)
{
    __shared__ float sWqm[64 * 32];
    __shared__ float sWkm[64 * 32];
    __shared__ float sWm [32 * 128];
    int tid = threadIdx.x;
    for (int i = tid; i < 64 * 32; i += 256) { sWqm[i] = Wqm[i]; sWkm[i] = Wkm[i]; }
    for (int i = tid; i < 32 * 128; i += 256) { sWm[i] = Wmetric[i]; }
    __syncthreads();

    const unsigned FULL = 0xffffffffu;
    int w = tid >> 5, lane = tid & 31;
    float invf = expf(-((float)(2 * lane) / 64.0f) * 9.210340371976184f);

    #pragma unroll 1
    for (int it = 0; it < 8; it++) {
        int tok = blockIdx.x * 64 + it * 8 + w;
        int tpos = tok & 511;

        const float* q = g_q + tok * 64;
        const float* k = g_k + tok * 64;
        float a0r = q[lane], a1r = q[lane + 32];
        float b0r = k[lane], b1r = k[lane + 32];

        // fused RoPE
        float s, c;
        sincosf((float)tpos * invf, &s, &c);
        float a0 = a0r * c - a1r * s;
        float a1 = a0r * s + a1r * c;
        float b0 = b0r * c - b1r * s;
        float b1 = b0r * s + b1r * c;

        // 2-way partial accumulators to break the FMA dependency chain
        float aq0 = 0.f, aq1 = 0.f, ak0 = 0.f, ak1 = 0.f;
        #pragma unroll
        for (int d = 0; d < 16; d++) {
            float qdA = __shfl_sync(FULL, a0, d);
            float kdA = __shfl_sync(FULL, b0, d);
            float qdB = __shfl_sync(FULL, a0, d + 16);
            float kdB = __shfl_sync(FULL, b0, d + 16);
            aq0 += qdA * sWqm[d * 32 + lane];
            ak0 += kdA * sWkm[d * 32 + lane];
            aq1 += qdB * sWqm[(d + 16) * 32 + lane];
            ak1 += kdB * sWkm[(d + 16) * 32 + lane];
        }
        #pragma unroll
        for (int d = 0; d < 16; d++) {
            float qdA = __shfl_sync(FULL, a1, d);
            float kdA = __shfl_sync(FULL, b1, d);
            float qdB = __shfl_sync(FULL, a1, d + 16);
            float kdB = __shfl_sync(FULL, b1, d + 16);
            aq0 += qdA * sWqm[(d + 32) * 32 + lane];
            ak0 += kdA * sWkm[(d + 32) * 32 + lane];
            aq1 += qdB * sWqm[(d + 48) * 32 + lane];
            ak1 += kdB * sWkm[(d + 48) * 32 + lane];
        }
        float accq = aq0 + aq1, acck = ak0 + ak1;
        float qmv = 1.f / (1.f + expf(-accq));
        float kmv = 1.f / (1.f + expf(-acck));
        g_km[tok * 32 + lane] = kmv;

        float q2 = qmv * qmv, k2 = kmv * kmv;
        #pragma unroll
        for (int o = 16; o > 0; o >>= 1) {
            q2 += __shfl_xor_sync(FULL, q2, o);
            k2 += __shfl_xor_sync(FULL, k2, o);
        }
        if (lane == 0) g_k2[tok] = k2;

        float u0a = 0.f, u1a = 0.f, u2a = 0.f, u3a = 0.f;
        float u0b = 0.f, u1b = 0.f, u2b = 0.f, u3b = 0.f;
        #pragma unroll
        for (int d = 0; d < 16; d++) {
            float qdA = __shfl_sync(FULL, qmv, d);
            float qdB = __shfl_sync(FULL, qmv, d + 16);
            float4 wA = *(const float4*)&sWm[d * 128 + lane * 4];
            float4 wB = *(const float4*)&sWm[(d + 16) * 128 + lane * 4];
            u0a += qdA * wA.x; u1a += qdA * wA.y; u2a += qdA * wA.z; u3a += qdA * wA.w;
            u0b += qdB * wB.x; u1b += qdB * wB.y; u2b += qdB * wB.z; u3b += qdB * wB.w;
        }
        float u0 = u0a + u0b, u1 = u1a + u1b, u2 = u2a + u2b, u3 = u3a + u3b;
        *(float4*)&g_U[tok * 128 + lane * 4] = make_float4(u0, u1, u2, u3);

        float p0 = u0 * qmv, p1 = u1 * qmv, p2 = u2 * qmv, p3 = u3 * qmv;
        #pragma unroll
        for (int o = 16; o > 0; o >>= 1) {
            p0 += __shfl_xor_sync(FULL, p0, o);
            p1 += __shfl_xor_sync(FULL, p1, o);
            p2 += __shfl_xor_sync(FULL, p2, o);
            p3 += __shfl_xor_sync(FULL, p3, o);
        }
        float wd = p0 * u0 + p1 * u1 + p2 * u2 + p3 * u3;
        g_m[tok * 32 + lane] = qmv + wd;
        if (lane == 0)
            g_c[tok] = q2 + p0 * p0 + p1 * p1 + p2 * p2 + p3 * p3;
    }
}

// ---------------- attention: tf32 scores + bf16-pair PV (R13, frozen) ----------
#define KM_STR 66
#define V_STR  66
#define P_STR  34
#define ATTN_SMEM ((32*KM_STR + 32*V_STR + 128*P_STR) * 8 + 64 * 4)

__global__ void __launch_bounds__(256) attn_mma(const float* __restrict__ temp_ptr)
{
    extern __shared__ uint2 smem[];
    uint2* sKm = smem;                         // [32][KM_STR]
    uint2* sV  = sKm + 32 * KM_STR;            // [32][V_STR]
    uint2* sP  = sV + 32 * V_STR;              // [128][P_STR]
    float* sK2 = (float*)(sP + 128 * P_STR);   // [64]

    int qt = 3 - (int)(blockIdx.x >> 1);
    int jc = blockIdx.x & 1;
    int bh = blockIdx.y;
    int tok0 = bh * 512 + qt * 128;

    int tid  = threadIdx.x;
    int lane = tid & 31;
    int wid  = tid >> 5;
    int g    = lane >> 2;
    int tg   = lane & 3;
    int r0w  = wid * 16;

    float invT = 1.0f / fmaxf(temp_ptr[0], 0.5f);

    int rA = tok0 + r0w + g;
    int rB = rA + 8;
    int iRelA = qt * 128 + r0w + g;
    int iRelB = iRelA + 8;

    uint2 mm[4][4];
    unsigned uf[4][4][4];
    #pragma unroll
    for (int kk = 0; kk < 4; kk++) {
        int d0 = kk * 8 + tg;
        mm[kk][0] = spl(g_m[rA * 32 + d0]);
        mm[kk][1] = spl(g_m[rB * 32 + d0]);
        mm[kk][2] = spl(g_m[rA * 32 + d0 + 4]);
        mm[kk][3] = spl(g_m[rB * 32 + d0 + 4]);
        float4 uA0 = *(const float4*)&g_U[rA * 128 + d0 * 4];
        float4 uB0 = *(const float4*)&g_U[rB * 128 + d0 * 4];
        float4 uA4 = *(const float4*)&g_U[rA * 128 + (d0 + 4) * 4];
        float4 uB4 = *(const float4*)&g_U[rB * 128 + (d0 + 4) * 4];
        #pragma unroll
        for (int r = 0; r < 4; r++) {
            uf[r][kk][0] = tf32of(((const float*)&uA0)[r]);
            uf[r][kk][1] = tf32of(((const float*)&uB0)[r]);
            uf[r][kk][2] = tf32of(((const float*)&uA4)[r]);
            uf[r][kk][3] = tf32of(((const float*)&uB4)[r]);
        }
    }
    float ci0 = g_c[rA], ci1 = g_c[rB];

    float cpv[8][4];
    #pragma unroll
    for (int nt = 0; nt < 8; nt++)
        #pragma unroll
        for (int e = 0; e < 4; e++) cpv[nt][e] = 0.f;
    float runs0 = 0.f, runs1 = 0.f;

    int sj   = tid >> 2;
    int sgrp = tid & 3;

    for (int jt = jc; jt <= 2 * qt + 1; jt += 2) {
        int j0 = jt * 64;
        int tokJ = bh * 512 + j0;
        __syncthreads();
        {
            float4 k0 = *(const float4*)&g_km[(tokJ + sj) * 32 + sgrp * 8];
            float4 k1 = *(const float4*)&g_km[(tokJ + sj) * 32 + sgrp * 8 + 4];
            #pragma unroll
            for (int t = 0; t < 4; t++)
                sKm[(sgrp * 8 + t) * KM_STR + sj] = spl(((const float*)&k0)[t]);
            #pragma unroll
            for (int t = 0; t < 4; t++)
                sKm[(sgrp * 8 + 4 + t) * KM_STR + sj] = spl(((const float*)&k1)[t]);
            if (tid < 64) sK2[tid] = g_k2[tokJ + tid];
        }
        #pragma unroll
        for (int e = 0; e < 2; e++) {
            int idx = tid + e * 256;
            int jp = idx >> 4, c4 = idx & 15;
            float4 v0 = *(const float4*)&g_v[(tokJ + 2 * jp) * 64 + c4 * 4];
            float4 v1 = *(const float4*)&g_v[(tokJ + 2 * jp + 1) * 64 + c4 * 4];
            uint2* d = &sV[jp * V_STR + c4 * 4];
            d[0] = sbf(v0.x, v1.x);
            d[1] = sbf(v0.y, v1.y);
            d[2] = sbf(v0.z, v1.z);
            d[3] = sbf(v0.w, v1.w);
        }
        __syncthreads();

        #pragma unroll
        for (int nt = 0; nt < 8; nt++) {
            float cqk[4] = {0.f, 0.f, 0.f, 0.f};
            float cu0[4] = {0.f, 0.f, 0.f, 0.f};
            float cu1[4] = {0.f, 0.f, 0.f, 0.f};
            float cu2[4] = {0.f, 0.f, 0.f, 0.f};
            float cu3[4] = {0.f, 0.f, 0.f, 0.f};
            #pragma unroll
            for (int kk = 0; kk < 4; kk++) {
                uint2 b0 = sKm[(kk * 8 + tg) * KM_STR + nt * 8 + g];
                uint2 b1 = sKm[(kk * 8 + tg + 4) * KM_STR + nt * 8 + g];
                mma8(cqk, mm[kk][0].x, mm[kk][1].x, mm[kk][2].x, mm[kk][3].x, b0.x, b1.x);
                mma8(cqk, mm[kk][0].x, mm[kk][1].x, mm[kk][2].x, mm[kk][3].x, b0.y, b1.y);
                mma8(cqk, mm[kk][0].y, mm[kk][1].y, mm[kk][2].y, mm[kk][3].y, b0.x, b1.x);
                mma8(cu0, uf[0][kk][0], uf[0][kk][1], uf[0][kk][2], uf[0][kk][3], b0.x, b1.x);
                mma8(cu1, uf[1][kk][0], uf[1][kk][1], uf[1][kk][2], uf[1][kk][3], b0.x, b1.x);
                mma8(cu2, uf[2][kk][0], uf[2][kk][1], uf[2][kk][2], uf[2][kk][3], b0.x, b1.x);
                mma8(cu3, uf[3][kk][0], uf[3][kk][1], uf[3][kk][2], uf[3][kk][3], b0.x, b1.x);
            }
            int colA = nt * 8 + 2 * tg;
            float2 k2p = *(const float2*)&sK2[colA];
            int jRelA = j0 + colA, jRelB = jRelA + 1;
            float p[4];
            #pragma unroll
            for (int e = 0; e < 4; e++) {
                float cival = (e < 2) ? ci0 : ci1;
                float k2v   = (e & 1) ? k2p.y : k2p.x;
                float dist = cival + k2v - 2.f * cqk[e]
                           + cu0[e] * cu0[e] + cu1[e] * cu1[e]
                           + cu2[e] * cu2[e] + cu3[e] * cu3[e];
                p[e] = __expf(-fmaxf(dist, 0.f) * invT);
            }
            if (jRelA > iRelA) p[0] = 0.f;
            if (jRelB > iRelA) p[1] = 0.f;
            if (jRelA > iRelB) p[2] = 0.f;
            if (jRelB > iRelB) p[3] = 0.f;
            runs0 += p[0] + p[1];
            runs1 += p[2] + p[3];
            int jpA = nt * 4 + tg;
            sP[(r0w + g) * P_STR + jpA]     = sbf(p[0], p[1]);
            sP[(r0w + g + 8) * P_STR + jpA] = sbf(p[2], p[3]);
        }
        __syncwarp();

        #pragma unroll
        for (int kk = 0; kk < 4; kk++) {
            uint2 A0 = sP[(r0w + g) * P_STR + kk * 8 + tg];
            uint2 A1 = sP[(r0w + g + 8) * P_STR + kk * 8 + tg];
            uint2 A2 = sP[(r0w + g) * P_STR + kk * 8 + tg + 4];
            uint2 A3 = sP[(r0w + g + 8) * P_STR + kk * 8 + tg + 4];
            #pragma unroll
            for (int nt = 0; nt < 8; nt++) {
                uint2 b0 = sV[(kk * 8 + tg) * V_STR + nt * 8 + g];
                uint2 b1 = sV[(kk * 8 + tg + 4) * V_STR + nt * 8 + g];
                mma16(cpv[nt], A0.x, A1.x, A2.x, A3.x, b0.x, b1.x);
                mma16(cpv[nt], A0.x, A1.x, A2.x, A3.x, b0.y, b1.y);
                mma16(cpv[nt], A0.y, A1.y, A2.y, A3.y, b0.x, b1.x);
            }
        }
    }

    const unsigned FULL = 0xffffffffu;
    float s0 = runs0, s1 = runs1;
    s0 += __shfl_xor_sync(FULL, s0, 1); s0 += __shfl_xor_sync(FULL, s0, 2);
    s1 += __shfl_xor_sync(FULL, s1, 1); s1 += __shfl_xor_sync(FULL, s1, 2);
    if (tg == 0) {
        g_psum[jc][rA] = s0;
        g_psum[jc][rB] = s1;
    }
    #pragma unroll
    for (int nt = 0; nt < 8; nt++) {
        int col = nt * 8 + 2 * tg;
        *(float2*)&g_pacc[jc][(size_t)rA * 64 + col] = make_float2(cpv[nt][0], cpv[nt][1]);
        *(float2*)&g_pacc[jc][(size_t)rB * 64 + col] = make_float2(cpv[nt][2], cpv[nt][3]);
    }
}

// ---------------- merge partials -> g_xs (bf16 split, ready for mode-1 GEMM) ---
__global__ void merge_kernel()
{
    int idx = blockIdx.x * 256 + threadIdx.x;    // 262144 items
    int tok = idx >> 4, c4 = idx & 15;
    int i = tok & 511;
    float4 a = *(const float4*)&g_pacc[0][tok * 64 + c4 * 4];
    float s = g_psum[0][tok];
    int iq = i & 127;
    if (iq >= 64 || i >= 128) {
        float4 b = *(const float4*)&g_pacc[1][tok * 64 + c4 * 4];
        a.x += b.x; a.y += b.y; a.z += b.z; a.w += b.w;
        s += g_psum[1][tok];
    }
    float inv = 1.f / s;
    int bh = tok >> 9;
    int b = bh >> 4, h = bh & 15;
    int row = b * 512 + i;
    int kp = (h * 64 + c4 * 4) >> 1;
    g_xs[row * 512 + kp]     = sbf(a.x * inv, a.y * inv);
    g_xs[row * 512 + kp + 1] = sbf(a.z * inv, a.w * inv);
}

// ---------------- launch ------------------------------------------------------
extern "C" void kernel_launch(void* const* d_in, const int* in_sizes, int n_in,
                              void* d_out, int out_size)
{
    const float* x    = (const float*)d_in[0];
    const float* Wq   = (const float*)d_in[1];
    const float* Wk   = (const float*)d_in[2];
    const float* Wv   = (const float*)d_in[3];
    const float* Wo   = (const float*)d_in[4];
    const float* Wqm  = (const float*)d_in[5];
    const float* Wkm  = (const float*)d_in[6];
    const float* Wmet = (const float*)d_in[7];
    const float* temp = (const float*)d_in[8];
    float*       out  = (float*)d_out;

    cudaFuncSetAttribute(gemm_tc,
                         cudaFuncAttributeMaxDynamicSharedMemorySize, GEMM_SMEM);
    cudaFuncSetAttribute(attn_mma,
                         cudaFuncAttributeMaxDynamicSharedMemorySize, ATTN_SMEM);

    uint2 *xs;
    cudaGetSymbolAddress((void**)&xs, g_xs);

    splitA<<<512, 256>>>(x, xs);
    splitW4<<<2048, 256>>>(Wq, Wk, Wv, Wo);

    gemm_tc<<<dim3(16, 8, 3), 256, GEMM_SMEM>>>(nullptr, 0);
    metric_kernel<<<BHT / 64, 256>>>(Wqm, Wkm, Wmet);
    attn_mma<<<dim3(8, Bb * Hh), 256, ATTN_SMEM>>>(temp);
    merge_kernel<<<1024, 256>>>();
    gemm_tc<<<dim3(16, 8, 1), 256, GEMM_SMEM>>>(out, 1);
}

// round 17
// speedup vs baseline: 1.4145x; 1.0007x over previous
#include <cuda_runtime.h>
#include <math.h>

#define Bb   2
#define Tt   512
#define Hh   16
#define BHT  16384
#define MSZ  (1024*1024)

// ---------------- scratch ----------------------------------------------------
__device__ float g_q [BHT*64];
__device__ float g_k [BHT*64];
__device__ float g_v [BHT*64];
__device__ float g_km[BHT*32];
__device__ float g_k2[BHT];
__device__ float g_U [BHT*128];
__device__ float g_m [BHT*32];
__device__ float g_c [BHT];
__device__ float g_pacc[2][BHT*64];
__device__ float g_psum[2][BHT];
// bf16 split-packed operands: uint2 = (ah_pair, al_pair) per 2 k-elements
__device__ uint2 g_xs[MSZ/2];        // A  [1024 rows][512 kp]  (x, then attn out)
__device__ uint2 g_ws[4*(MSZ/2)];    // W  [512 kp][1024 n] x4

// ---------------- bf16 split helpers -------------------------------------------
__device__ __forceinline__ uint2 sbf(float a, float b) {
    unsigned ph;
    asm("cvt.rn.bf16x2.f32 %0,%1,%2;" : "=r"(ph) : "f"(b), "f"(a));
    float ra = a - __uint_as_float(ph << 16);
    float rb = b - __uint_as_float(ph & 0xffff0000u);
    unsigned pl;
    asm("cvt.rn.bf16x2.f32 %0,%1,%2;" : "=r"(pl) : "f"(rb), "f"(ra));
    return make_uint2(ph, pl);
}

// ---------------- tf32 helpers (attention scores) -------------------------------
__device__ __forceinline__ unsigned tf32of(float x) {
    unsigned r; asm("cvt.rna.tf32.f32 %0,%1;" : "=r"(r) : "f"(x)); return r;
}
__device__ __forceinline__ uint2 spl(float x) {
    unsigned h = tf32of(x);
    unsigned l = tf32of(x - __uint_as_float(h));
    return make_uint2(h, l);
}
__device__ __forceinline__ void mma8(float* c,
    unsigned a0, unsigned a1, unsigned a2, unsigned a3,
    unsigned b0, unsigned b1)
{
    asm volatile(
        "mma.sync.aligned.m16n8k8.row.col.f32.tf32.tf32.f32 "
        "{%0,%1,%2,%3},{%4,%5,%6,%7},{%8,%9},{%0,%1,%2,%3};"
        : "+f"(c[0]), "+f"(c[1]), "+f"(c[2]), "+f"(c[3])
        : "r"(a0), "r"(a1), "r"(a2), "r"(a3), "r"(b0), "r"(b1));
}
__device__ __forceinline__ void mma16(float* c,
    unsigned a0, unsigned a1, unsigned a2, unsigned a3,
    unsigned b0, unsigned b1)
{
    asm volatile(
        "mma.sync.aligned.m16n8k16.row.col.f32.bf16.bf16.f32 "
        "{%0,%1,%2,%3},{%4,%5,%6,%7},{%8,%9},{%0,%1,%2,%3};"
        : "+f"(c[0]), "+f"(c[1]), "+f"(c[2]), "+f"(c[3])
        : "r"(a0), "r"(a1), "r"(a2), "r"(a3), "r"(b0), "r"(b1));
}

// ---------------- split kernels -------------------------------------------------
__global__ void splitA(const float* __restrict__ src, uint2* __restrict__ dst)
{
    int idx = blockIdx.x * 256 + threadIdx.x;
    float4 v0 = *(const float4*)&src[idx * 8];
    float4 v1 = *(const float4*)&src[idx * 8 + 4];
    dst[idx * 4 + 0] = sbf(v0.x, v0.y);
    dst[idx * 4 + 1] = sbf(v0.z, v0.w);
    dst[idx * 4 + 2] = sbf(v1.x, v1.y);
    dst[idx * 4 + 3] = sbf(v1.z, v1.w);
}

__global__ void splitW4(const float* __restrict__ W0, const float* __restrict__ W1,
                        const float* __restrict__ W2, const float* __restrict__ W3)
{
    int m = blockIdx.x >> 9;
    const float* W = (m == 0) ? W0 : (m == 1) ? W1 : (m == 2) ? W2 : W3;
    uint2* dst = g_ws + m * (MSZ / 2);
    int idx = (blockIdx.x & 511) * 256 + threadIdx.x;
    int kp = idx >> 8;
    int n4 = (idx & 255) * 4;
    float4 r0 = *(const float4*)&W[(2 * kp) * 1024 + n4];
    float4 r1 = *(const float4*)&W[(2 * kp + 1) * 1024 + n4];
    dst[kp * 1024 + n4 + 0] = sbf(r0.x, r1.x);
    dst[kp * 1024 + n4 + 1] = sbf(r0.y, r1.y);
    dst[kp * 1024 + n4 + 2] = sbf(r0.z, r1.z);
    dst[kp * 1024 + n4 + 3] = sbf(r0.w, r1.w);
}

// ---------------- GEMM (3x bf16, double-buffered, 2 blocks/SM) -----------------
#define SA_STR 18
#define SB_STR 68
#define BUF_SZ (128*SA_STR + 16*SB_STR)
#define GEMM_SMEM (2 * BUF_SZ * 8)

__global__ void __launch_bounds__(256, 2) gemm_tc(float* __restrict__ Cout, int mode)
{
    extern __shared__ uint2 sm2[];

    int z = blockIdx.z;
    const uint4* Wm = (const uint4*)(g_ws + (mode == 0 ? z : 3) * (MSZ/2));
    const uint4* Am = (const uint4*)g_xs;

    int tid  = threadIdx.x;
    int lane = tid & 31;
    int wid  = tid >> 5;
    int wm   = wid & 3;
    int wn   = wid >> 2;
    int g    = lane >> 2;
    int tg   = lane & 3;
    int row0 = blockIdx.y * 128;
    int col0 = blockIdx.x * 64;

    int aRow[4], aK4[4], sAi[4];
    #pragma unroll
    for (int e = 0; e < 4; e++) {
        int idx = tid + e * 256;
        aRow[e] = idx >> 3; aK4[e] = idx & 7;
        sAi[e]  = aRow[e] * SA_STR + aK4[e] * 2;
    }
    int bKp = tid >> 4, bC4 = tid & 15;
    int sBi = 128 * SA_STR + bKp * SB_STR + bC4 * 4;
    int bGi = bKp * 512 + col0 / 2 + bC4 * 2;

    float acc[2][4][4];
    #pragma unroll
    for (int mt = 0; mt < 2; mt++)
        #pragma unroll
        for (int nt = 0; nt < 4; nt++)
            #pragma unroll
            for (int e = 0; e < 4; e++) acc[mt][nt][e] = 0.f;

    uint4 av[4], bv0, bv1;
    #pragma unroll
    for (int e = 0; e < 4; e++)
        av[e] = Am[(row0 + aRow[e]) * 256 + aK4[e]];
    bv0 = Wm[bGi];
    bv1 = Wm[bGi + 1];

    {
        uint2* buf = sm2;
        #pragma unroll
        for (int e = 0; e < 4; e++)
            *(uint4*)&buf[sAi[e]] = av[e];
        *(uint4*)&buf[sBi]     = bv0;
        *(uint4*)&buf[sBi + 2] = bv1;
    }
    __syncthreads();

    for (int t = 0; t < 32; t++) {
        uint2* cur = sm2 + (t & 1) * BUF_SZ;
        uint2* nxt = sm2 + ((t & 1) ^ 1) * BUF_SZ;

        if (t < 31) {
            #pragma unroll
            for (int e = 0; e < 4; e++)
                av[e] = Am[(row0 + aRow[e]) * 256 + (t + 1) * 8 + aK4[e]];
            bv0 = Wm[(t + 1) * 16 * 512 + bGi];
            bv1 = Wm[(t + 1) * 16 * 512 + bGi + 1];
        }

        #pragma unroll
        for (int ks = 0; ks < 2; ks++) {
            uint2 Afr[2][4];
            #pragma unroll
            for (int mt = 0; mt < 2; mt++) {
                int rb = (wm * 32 + mt * 16 + g) * SA_STR + ks * 8 + tg;
                Afr[mt][0] = cur[rb];
                Afr[mt][2] = cur[rb + 4];
                Afr[mt][1] = cur[rb + 8 * SA_STR];
                Afr[mt][3] = cur[rb + 8 * SA_STR + 4];
            }
            #pragma unroll
            for (int nt = 0; nt < 4; nt++) {
                int cb = 128 * SA_STR + (ks * 8 + tg) * SB_STR + wn * 32 + nt * 8 + g;
                uint2 B0 = cur[cb];
                uint2 B1 = cur[cb + 4 * SB_STR];
                #pragma unroll
                for (int mt = 0; mt < 2; mt++) {
                    float* c = acc[mt][nt];
                    mma16(c, Afr[mt][0].x, Afr[mt][1].x, Afr[mt][2].x, Afr[mt][3].x,
                          B0.x, B1.x);
                    mma16(c, Afr[mt][0].x, Afr[mt][1].x, Afr[mt][2].x, Afr[mt][3].x,
                          B0.y, B1.y);
                    mma16(c, Afr[mt][0].y, Afr[mt][1].y, Afr[mt][2].y, Afr[mt][3].y,
                          B0.x, B1.x);
                }
            }
        }

        if (t < 31) {
            #pragma unroll
            for (int e = 0; e < 4; e++)
                *(uint4*)&nxt[sAi[e]] = av[e];
            *(uint4*)&nxt[sBi]     = bv0;
            *(uint4*)&nxt[sBi + 2] = bv1;
        }
        __syncthreads();
    }

    if (mode == 1) {
        #pragma unroll
        for (int mt = 0; mt < 2; mt++) {
            int row = row0 + wm * 32 + mt * 16 + g;
            #pragma unroll
            for (int nt = 0; nt < 4; nt++) {
                int col = col0 + wn * 32 + nt * 8 + 2 * tg;
                *(float2*)&Cout[row * 1024 + col] =
                    make_float2(acc[mt][nt][0], acc[mt][nt][1]);
                *(float2*)&Cout[(row + 8) * 1024 + col] =
                    make_float2(acc[mt][nt][2], acc[mt][nt][3]);
            }
        }
    } else {
        float* dst = (z == 0) ? g_q : (z == 1) ? g_k : g_v;
        int h = blockIdx.x;
        #pragma unroll
        for (int mt = 0; mt < 2; mt++) {
            int row = row0 + wm * 32 + mt * 16 + g;
            int b0r = row >> 9, t0r = row & 511;
            int b1r = (row + 8) >> 9, t1r = (row + 8) & 511;
            #pragma unroll
            for (int nt = 0; nt < 4; nt++) {
                int col = wn * 32 + nt * 8 + 2 * tg;
                *(float2*)&dst[(((b0r << 4) + h) * 512 + t0r) * 64 + col] =
                    make_float2(acc[mt][nt][0], acc[mt][nt][1]);
                *(float2*)&dst[(((b1r << 4) + h) * 512 + t1r) * 64 + col] =
                    make_float2(acc[mt][nt][2], acc[mt][nt][3]);
            }
        }
    }
}

// ---------------- metric with fused RoPE, 32 tokens/block ----------------------
__global__ void __launch_bounds__(256) metric_kernel(
    const float* __restrict__ Wqm, const float* __restrict__ Wkm,
    const float* __restrict__ Wmetric)
{
    __shared__ float sWqm[64 * 32];
    __shared__ float sWkm[64 * 32];
    __shared__ float sWm [32 * 128];
    int tid = threadIdx.x;
    for (int i = tid; i < 64 * 32; i += 256) { sWqm[i] = Wqm[i]; sWkm[i] = Wkm[i]; }
    for (int i = tid; i < 32 * 128; i += 256) { sWm[i] = Wmetric[i]; }
    __syncthreads();

    const unsigned FULL = 0xffffffffu;
    int w = tid >> 5, lane = tid & 31;
    float invf = expf(-((float)(2 * lane) / 64.0f) * 9.210340371976184f);

    #pragma unroll 1
    for (int it = 0; it < 4; it++) {
        int tok = blockIdx.x * 32 + it * 8 + w;
        int tpos = tok & 511;

        const float* q = g_q + tok * 64;
        const float* k = g_k + tok * 64;
        float a0r = q[lane], a1r = q[lane + 32];
        float b0r = k[lane], b1r = k[lane + 32];

        // fused RoPE
        float s, c;
        sincosf((float)tpos * invf, &s, &c);
        float a0 = a0r * c - a1r * s;
        float a1 = a0r * s + a1r * c;
        float b0 = b0r * c - b1r * s;
        float b1 = b0r * s + b1r * c;

        // 2-way partial accumulators to break the FMA dependency chain
        float aq0 = 0.f, aq1 = 0.f, ak0 = 0.f, ak1 = 0.f;
        #pragma unroll
        for (int d = 0; d < 16; d++) {
            float qdA = __shfl_sync(FULL, a0, d);
            float kdA = __shfl_sync(FULL, b0, d);
            float qdB = __shfl_sync(FULL, a0, d + 16);
            float kdB = __shfl_sync(FULL, b0, d + 16);
            aq0 += qdA * sWqm[d * 32 + lane];
            ak0 += kdA * sWkm[d * 32 + lane];
            aq1 += qdB * sWqm[(d + 16) * 32 + lane];
            ak1 += kdB * sWkm[(d + 16) * 32 + lane];
        }
        #pragma unroll
        for (int d = 0; d < 16; d++) {
            float qdA = __shfl_sync(FULL, a1, d);
            float kdA = __shfl_sync(FULL, b1, d);
            float qdB = __shfl_sync(FULL, a1, d + 16);
            float kdB = __shfl_sync(FULL, b1, d + 16);
            aq0 += qdA * sWqm[(d + 32) * 32 + lane];
            ak0 += kdA * sWkm[(d + 32) * 32 + lane];
            aq1 += qdB * sWqm[(d + 48) * 32 + lane];
            ak1 += kdB * sWkm[(d + 48) * 32 + lane];
        }
        float accq = aq0 + aq1, acck = ak0 + ak1;
        float qmv = 1.f / (1.f + expf(-accq));
        float kmv = 1.f / (1.f + expf(-acck));
        g_km[tok * 32 + lane] = kmv;

        float q2 = qmv * qmv, k2 = kmv * kmv;
        #pragma unroll
        for (int o = 16; o > 0; o >>= 1) {
            q2 += __shfl_xor_sync(FULL, q2, o);
            k2 += __shfl_xor_sync(FULL, k2, o);
        }
        if (lane == 0) g_k2[tok] = k2;

        float u0a = 0.f, u1a = 0.f, u2a = 0.f, u3a = 0.f;
        float u0b = 0.f, u1b = 0.f, u2b = 0.f, u3b = 0.f;
        #pragma unroll
        for (int d = 0; d < 16; d++) {
            float qdA = __shfl_sync(FULL, qmv, d);
            float qdB = __shfl_sync(FULL, qmv, d + 16);
            float4 wA = *(const float4*)&sWm[d * 128 + lane * 4];
            float4 wB = *(const float4*)&sWm[(d + 16) * 128 + lane * 4];
            u0a += qdA * wA.x; u1a += qdA * wA.y; u2a += qdA * wA.z; u3a += qdA * wA.w;
            u0b += qdB * wB.x; u1b += qdB * wB.y; u2b += qdB * wB.z; u3b += qdB * wB.w;
        }
        float u0 = u0a + u0b, u1 = u1a + u1b, u2 = u2a + u2b, u3 = u3a + u3b;
        *(float4*)&g_U[tok * 128 + lane * 4] = make_float4(u0, u1, u2, u3);

        float p0 = u0 * qmv, p1 = u1 * qmv, p2 = u2 * qmv, p3 = u3 * qmv;
        #pragma unroll
        for (int o = 16; o > 0; o >>= 1) {
            p0 += __shfl_xor_sync(FULL, p0, o);
            p1 += __shfl_xor_sync(FULL, p1, o);
            p2 += __shfl_xor_sync(FULL, p2, o);
            p3 += __shfl_xor_sync(FULL, p3, o);
        }
        float wd = p0 * u0 + p1 * u1 + p2 * u2 + p3 * u3;
        g_m[tok * 32 + lane] = qmv + wd;
        if (lane == 0)
            g_c[tok] = q2 + p0 * p0 + p1 * p1 + p2 * p2 + p3 * p3;
    }
}

// ---------------- attention: tf32 scores + bf16-pair PV (R13, frozen) ----------
#define KM_STR 66
#define V_STR  66
#define P_STR  34
#define ATTN_SMEM ((32*KM_STR + 32*V_STR + 128*P_STR) * 8 + 64 * 4)

__global__ void __launch_bounds__(256) attn_mma(const float* __restrict__ temp_ptr)
{
    extern __shared__ uint2 smem[];
    uint2* sKm = smem;                         // [32][KM_STR]
    uint2* sV  = sKm + 32 * KM_STR;            // [32][V_STR]
    uint2* sP  = sV + 32 * V_STR;              // [128][P_STR]
    float* sK2 = (float*)(sP + 128 * P_STR);   // [64]

    int qt = 3 - (int)(blockIdx.x >> 1);
    int jc = blockIdx.x & 1;
    int bh = blockIdx.y;
    int tok0 = bh * 512 + qt * 128;

    int tid  = threadIdx.x;
    int lane = tid & 31;
    int wid  = tid >> 5;
    int g    = lane >> 2;
    int tg   = lane & 3;
    int r0w  = wid * 16;

    float invT = 1.0f / fmaxf(temp_ptr[0], 0.5f);

    int rA = tok0 + r0w + g;
    int rB = rA + 8;
    int iRelA = qt * 128 + r0w + g;
    int iRelB = iRelA + 8;

    uint2 mm[4][4];
    unsigned uf[4][4][4];
    #pragma unroll
    for (int kk = 0; kk < 4; kk++) {
        int d0 = kk * 8 + tg;
        mm[kk][0] = spl(g_m[rA * 32 + d0]);
        mm[kk][1] = spl(g_m[rB * 32 + d0]);
        mm[kk][2] = spl(g_m[rA * 32 + d0 + 4]);
        mm[kk][3] = spl(g_m[rB * 32 + d0 + 4]);
        float4 uA0 = *(const float4*)&g_U[rA * 128 + d0 * 4];
        float4 uB0 = *(const float4*)&g_U[rB * 128 + d0 * 4];
        float4 uA4 = *(const float4*)&g_U[rA * 128 + (d0 + 4) * 4];
        float4 uB4 = *(const float4*)&g_U[rB * 128 + (d0 + 4) * 4];
        #pragma unroll
        for (int r = 0; r < 4; r++) {
            uf[r][kk][0] = tf32of(((const float*)&uA0)[r]);
            uf[r][kk][1] = tf32of(((const float*)&uB0)[r]);
            uf[r][kk][2] = tf32of(((const float*)&uA4)[r]);
            uf[r][kk][3] = tf32of(((const float*)&uB4)[r]);
        }
    }
    float ci0 = g_c[rA], ci1 = g_c[rB];

    float cpv[8][4];
    #pragma unroll
    for (int nt = 0; nt < 8; nt++)
        #pragma unroll
        for (int e = 0; e < 4; e++) cpv[nt][e] = 0.f;
    float runs0 = 0.f, runs1 = 0.f;

    int sj   = tid >> 2;
    int sgrp = tid & 3;

    for (int jt = jc; jt <= 2 * qt + 1; jt += 2) {
        int j0 = jt * 64;
        int tokJ = bh * 512 + j0;
        __syncthreads();
        {
            float4 k0 = *(const float4*)&g_km[(tokJ + sj) * 32 + sgrp * 8];
            float4 k1 = *(const float4*)&g_km[(tokJ + sj) * 32 + sgrp * 8 + 4];
            #pragma unroll
            for (int t = 0; t < 4; t++)
                sKm[(sgrp * 8 + t) * KM_STR + sj] = spl(((const float*)&k0)[t]);
            #pragma unroll
            for (int t = 0; t < 4; t++)
                sKm[(sgrp * 8 + 4 + t) * KM_STR + sj] = spl(((const float*)&k1)[t]);
            if (tid < 64) sK2[tid] = g_k2[tokJ + tid];
        }
        #pragma unroll
        for (int e = 0; e < 2; e++) {
            int idx = tid + e * 256;
            int jp = idx >> 4, c4 = idx & 15;
            float4 v0 = *(const float4*)&g_v[(tokJ + 2 * jp) * 64 + c4 * 4];
            float4 v1 = *(const float4*)&g_v[(tokJ + 2 * jp + 1) * 64 + c4 * 4];
            uint2* d = &sV[jp * V_STR + c4 * 4];
            d[0] = sbf(v0.x, v1.x);
            d[1] = sbf(v0.y, v1.y);
            d[2] = sbf(v0.z, v1.z);
            d[3] = sbf(v0.w, v1.w);
        }
        __syncthreads();

        #pragma unroll
        for (int nt = 0; nt < 8; nt++) {
            float cqk[4] = {0.f, 0.f, 0.f, 0.f};
            float cu0[4] = {0.f, 0.f, 0.f, 0.f};
            float cu1[4] = {0.f, 0.f, 0.f, 0.f};
            float cu2[4] = {0.f, 0.f, 0.f, 0.f};
            float cu3[4] = {0.f, 0.f, 0.f, 0.f};
            #pragma unroll
            for (int kk = 0; kk < 4; kk++) {
                uint2 b0 = sKm[(kk * 8 + tg) * KM_STR + nt * 8 + g];
                uint2 b1 = sKm[(kk * 8 + tg + 4) * KM_STR + nt * 8 + g];
                mma8(cqk, mm[kk][0].x, mm[kk][1].x, mm[kk][2].x, mm[kk][3].x, b0.x, b1.x);
                mma8(cqk, mm[kk][0].x, mm[kk][1].x, mm[kk][2].x, mm[kk][3].x, b0.y, b1.y);
                mma8(cqk, mm[kk][0].y, mm[kk][1].y, mm[kk][2].y, mm[kk][3].y, b0.x, b1.x);
                mma8(cu0, uf[0][kk][0], uf[0][kk][1], uf[0][kk][2], uf[0][kk][3], b0.x, b1.x);
                mma8(cu1, uf[1][kk][0], uf[1][kk][1], uf[1][kk][2], uf[1][kk][3], b0.x, b1.x);
                mma8(cu2, uf[2][kk][0], uf[2][kk][1], uf[2][kk][2], uf[2][kk][3], b0.x, b1.x);
                mma8(cu3, uf[3][kk][0], uf[3][kk][1], uf[3][kk][2], uf[3][kk][3], b0.x, b1.x);
            }
            int colA = nt * 8 + 2 * tg;
            float2 k2p = *(const float2*)&sK2[colA];
            int jRelA = j0 + colA, jRelB = jRelA + 1;
            float p[4];
            #pragma unroll
            for (int e = 0; e < 4; e++) {
                float cival = (e < 2) ? ci0 : ci1;
                float k2v   = (e & 1) ? k2p.y : k2p.x;
                float dist = cival + k2v - 2.f * cqk[e]
                           + cu0[e] * cu0[e] + cu1[e] * cu1[e]
                           + cu2[e] * cu2[e] + cu3[e] * cu3[e];
                p[e] = __expf(-fmaxf(dist, 0.f) * invT);
            }
            if (jRelA > iRelA) p[0] = 0.f;
            if (jRelB > iRelA) p[1] = 0.f;
            if (jRelA > iRelB) p[2] = 0.f;
            if (jRelB > iRelB) p[3] = 0.f;
            runs0 += p[0] + p[1];
            runs1 += p[2] + p[3];
            int jpA = nt * 4 + tg;
            sP[(r0w + g) * P_STR + jpA]     = sbf(p[0], p[1]);
            sP[(r0w + g + 8) * P_STR + jpA] = sbf(p[2], p[3]);
        }
        __syncwarp();

        #pragma unroll
        for (int kk = 0; kk < 4; kk++) {
            uint2 A0 = sP[(r0w + g) * P_STR + kk * 8 + tg];
            uint2 A1 = sP[(r0w + g + 8) * P_STR + kk * 8 + tg];
            uint2 A2 = sP[(r0w + g) * P_STR + kk * 8 + tg + 4];
            uint2 A3 = sP[(r0w + g + 8) * P_STR + kk * 8 + tg + 4];
            #pragma unroll
            for (int nt = 0; nt < 8; nt++) {
                uint2 b0 = sV[(kk * 8 + tg) * V_STR + nt * 8 + g];
                uint2 b1 = sV[(kk * 8 + tg + 4) * V_STR + nt * 8 + g];
                mma16(cpv[nt], A0.x, A1.x, A2.x, A3.x, b0.x, b1.x);
                mma16(cpv[nt], A0.x, A1.x, A2.x, A3.x, b0.y, b1.y);
                mma16(cpv[nt], A0.y, A1.y, A2.y, A3.y, b0.x, b1.x);
            }
        }
    }

    const unsigned FULL = 0xffffffffu;
    float s0 = runs0, s1 = runs1;
    s0 += __shfl_xor_sync(FULL, s0, 1); s0 += __shfl_xor_sync(FULL, s0, 2);
    s1 += __shfl_xor_sync(FULL, s1, 1); s1 += __shfl_xor_sync(FULL, s1, 2);
    if (tg == 0) {
        g_psum[jc][rA] = s0;
        g_psum[jc][rB] = s1;
    }
    #pragma unroll
    for (int nt = 0; nt < 8; nt++) {
        int col = nt * 8 + 2 * tg;
        *(float2*)&g_pacc[jc][(size_t)rA * 64 + col] = make_float2(cpv[nt][0], cpv[nt][1]);
        *(float2*)&g_pacc[jc][(size_t)rB * 64 + col] = make_float2(cpv[nt][2], cpv[nt][3]);
    }
}

// ---------------- merge partials -> g_xs (bf16 split, ready for mode-1 GEMM) ---
__global__ void merge_kernel()
{
    int idx = blockIdx.x * 256 + threadIdx.x;    // 262144 items
    int tok = idx >> 4, c4 = idx & 15;
    int i = tok & 511;
    float4 a = *(const float4*)&g_pacc[0][tok * 64 + c4 * 4];
    float s = g_psum[0][tok];
    int iq = i & 127;
    if (iq >= 64 || i >= 128) {
        float4 b = *(const float4*)&g_pacc[1][tok * 64 + c4 * 4];
        a.x += b.x; a.y += b.y; a.z += b.z; a.w += b.w;
        s += g_psum[1][tok];
    }
    float inv = 1.f / s;
    int bh = tok >> 9;
    int b = bh >> 4, h = bh & 15;
    int row = b * 512 + i;
    int kp = (h * 64 + c4 * 4) >> 1;
    g_xs[row * 512 + kp]     = sbf(a.x * inv, a.y * inv);
    g_xs[row * 512 + kp + 1] = sbf(a.z * inv, a.w * inv);
}

// ---------------- launch ------------------------------------------------------
extern "C" void kernel_launch(void* const* d_in, const int* in_sizes, int n_in,
                              void* d_out, int out_size)
{
    const float* x    = (const float*)d_in[0];
    const float* Wq   = (const float*)d_in[1];
    const float* Wk   = (const float*)d_in[2];
    const float* Wv   = (const float*)d_in[3];
    const float* Wo   = (const float*)d_in[4];
    const float* Wqm  = (const float*)d_in[5];
    const float* Wkm  = (const float*)d_in[6];
    const float* Wmet = (const float*)d_in[7];
    const float* temp = (const float*)d_in[8];
    float*       out  = (float*)d_out;

    cudaFuncSetAttribute(gemm_tc,
                         cudaFuncAttributeMaxDynamicSharedMemorySize, GEMM_SMEM);
    cudaFuncSetAttribute(attn_mma,
                         cudaFuncAttributeMaxDynamicSharedMemorySize, ATTN_SMEM);

    uint2 *xs;
    cudaGetSymbolAddress((void**)&xs, g_xs);

    splitA<<<512, 256>>>(x, xs);
    splitW4<<<2048, 256>>>(Wq, Wk, Wv, Wo);

    gemm_tc<<<dim3(16, 8, 3), 256, GEMM_SMEM>>>(nullptr, 0);
    metric_kernel<<<BHT / 32, 256>>>(Wqm, Wkm, Wmet);
    attn_mma<<<dim3(8, Bb * Hh), 256, ATTN_SMEM>>>(temp);
    merge_kernel<<<1024, 256>>>();
    gemm_tc<<<dim3(16, 8, 1), 256, GEMM_SMEM>>>(out, 1);
}